// round 12
// baseline (speedup 1.0000x reference)
#include <cuda_runtime.h>
#include <cstdint>

// ---------------- problem constants ----------------
#define NB     8
#define NC     128
#define NHW    16384            // 128*128
#define NHEADS 8
#define HD     16               // head dim (channels per head)
#define NELEM  16777216         // NB*NC*NHW
#define NS     16               // gram n-split

#define FPITCH 129              // 128x128 fft tile pitch (float2)

// ---------------- scratch (device globals; no allocs allowed) ----------------
__device__ float2 d_xf[NELEM];      // fft2(x)
__device__ float2 d_work[NELEM];    // out_cplx(post ifft16) / g*xf / qkv temps
__device__ float  d_outf[NELEM];    // |ifft2(out_cplx)|
__device__ float  d_outfl[NELEM];   // |ifft2(g*xf)|
__device__ float  d_q[NELEM];
__device__ float  d_k[NELEM];
__device__ float  d_v[NELEM];
__device__ float  d_outsl[NELEM];
__device__ float  d_bufT[NELEM];    // qkv temp, then out_s
__device__ float2 d_attnf[NB*NHEADS*HD*HD];
__device__ float  d_attns[NB*NHEADS*HD*HD];
// gram partials
__device__ float2 d_gfp[NB*NHEADS*NS*256];
__device__ float  d_gfn[NB*NHEADS*NS*16];
__device__ float  d_gsp[NB*NHEADS*NS*256];
__device__ float  d_gsq[NB*NHEADS*NS*16];
__device__ float  d_gsk[NB*NHEADS*NS*16];

// ---------------- helpers ----------------
__device__ __forceinline__ float2 cmul(float2 a, float2 b) {
    return make_float2(a.x*b.x - a.y*b.y, a.x*b.y + a.y*b.x);
}
__device__ __forceinline__ float2 cadd(float2 a, float2 b) { return make_float2(a.x+b.x, a.y+b.y); }
__device__ __forceinline__ float2 csub(float2 a, float2 b) { return make_float2(a.x-b.x, a.y-b.y); }
__device__ __forceinline__ int brev7(int v) { return __brev(v) >> 25; }

// ---- packed fp32x2 (Blackwell FFMA2 path) ----
__device__ __forceinline__ unsigned long long pk2(float a, float b) {
    unsigned long long r;
    asm("mov.b64 %0, {%1, %2};" : "=l"(r) : "f"(a), "f"(b));
    return r;
}
__device__ __forceinline__ void ffma2(unsigned long long& c, unsigned long long a, unsigned long long b) {
    asm("fma.rn.f32x2 %0, %1, %2, %0;" : "+l"(c) : "l"(a), "l"(b));
}
__device__ __forceinline__ float2 upk2(unsigned long long v) {
    float2 r;
    asm("mov.b64 {%0, %1}, %2;" : "=f"(r.x), "=f"(r.y) : "l"(v));
    return r;
}

// ============ 2D 128x128 FFT (radix-2^2), NATURAL-order input ============
// tw[j] = exp(dir*i*pi*j/64), j in [0,64). NT = threads.
// In-smem bank-clean bit-reverse permutes; column stages ROW-FAST (R5-proven).
template <int NT>
__device__ void fft2_128_r4(float2* s, const float2* tw, int tid) {
    // ---- column bit-reverse permute (r fast: conflict-free) ----
    for (int idx = tid; idx < 16384; idx += NT) {
        int r = idx & 127, c = idx >> 7;
        int rc = brev7(c);
        if (c < rc) {
            float2 t = s[r*FPITCH + c];
            s[r*FPITCH + c]  = s[r*FPITCH + rc];
            s[r*FPITCH + rc] = t;
        }
    }
    __syncthreads();
    // ---- column stages, row-fast ----
    #pragma unroll
    for (int st = 0; st < 6; st += 2) {
        int h = 1 << st;
        for (int idx = tid; idx < 4096; idx += NT) {
            int r = idx & 127, j = idx >> 7;      // j in [0,32)
            int pos = j & (h - 1);
            int q = ((j >> st) << (st + 2)) + pos;
            float2* row = s + r * FPITCH;
            float2 a = row[q], b = row[q+h], c = row[q+2*h], d = row[q+3*h];
            float2 w1 = tw[pos << (6 - st)];
            float2 t  = cmul(b, w1);
            float2 u0 = cadd(a, t), u1 = csub(a, t);
            float2 t2 = cmul(d, w1);
            float2 u2 = cadd(c, t2), u3 = csub(c, t2);
            float2 w2 = tw[pos << (5 - st)];
            float2 w3 = tw[(pos + h) << (5 - st)];
            float2 v  = cmul(u2, w2);
            row[q]       = cadd(u0, v);
            row[q+2*h]   = csub(u0, v);
            float2 v2 = cmul(u3, w3);
            row[q+h]     = cadd(u1, v2);
            row[q+3*h]   = csub(u1, v2);
        }
        __syncthreads();
    }
    for (int idx = tid; idx < 8192; idx += NT) {
        int r = idx & 127, pos = idx >> 7;        // pos in [0,64)
        float2 w = tw[pos];
        float2* p0 = &s[r*FPITCH + pos];
        float2* p1 = &s[r*FPITCH + pos + 64];
        float2 a = *p0, t = cmul(*p1, w);
        *p0 = cadd(a, t);
        *p1 = csub(a, t);
    }
    __syncthreads();
    // ---- row bit-reverse permute (c fast: conflict-free) ----
    for (int idx = tid; idx < 16384; idx += NT) {
        int c = idx & 127, r = idx >> 7;
        int rr = brev7(r);
        if (r < rr) {
            float2 t = s[r*FPITCH + c];
            s[r*FPITCH + c]  = s[rr*FPITCH + c];
            s[rr*FPITCH + c] = t;
        }
    }
    __syncthreads();
    // ---- row stages, column-fast ----
    #pragma unroll
    for (int st = 0; st < 6; st += 2) {
        int h = 1 << st;
        for (int idx = tid; idx < 4096; idx += NT) {
            int c0 = idx & 127, j = idx >> 7;
            int pos = j & (h - 1);
            int q = ((j >> st) << (st + 2)) + pos;
            float2 a = s[(q      )*FPITCH + c0];
            float2 b = s[(q +   h)*FPITCH + c0];
            float2 c = s[(q + 2*h)*FPITCH + c0];
            float2 d = s[(q + 3*h)*FPITCH + c0];
            float2 w1 = tw[pos << (6 - st)];
            float2 t  = cmul(b, w1);
            float2 u0 = cadd(a, t), u1 = csub(a, t);
            float2 t2 = cmul(d, w1);
            float2 u2 = cadd(c, t2), u3 = csub(c, t2);
            float2 w2 = tw[pos << (5 - st)];
            float2 w3 = tw[(pos + h) << (5 - st)];
            float2 v  = cmul(u2, w2);
            s[(q      )*FPITCH + c0] = cadd(u0, v);
            s[(q + 2*h)*FPITCH + c0] = csub(u0, v);
            float2 v2 = cmul(u3, w3);
            s[(q +   h)*FPITCH + c0] = cadd(u1, v2);
            s[(q + 3*h)*FPITCH + c0] = csub(u1, v2);
        }
        __syncthreads();
    }
    for (int idx = tid; idx < 8192; idx += NT) {
        int c0 = idx & 127, pos = idx >> 7;
        float2 w = tw[pos];
        float2* p0 = &s[pos*FPITCH + c0];
        float2* p1 = &s[(pos + 64)*FPITCH + c0];
        float2 a = *p0, t = cmul(*p1, w);
        *p0 = cadd(a, t);
        *p1 = csub(a, t);
    }
    __syncthreads();
}

// ---------------- forward FFT2 of x -> d_xf (natural coalesced load) ----------------
__global__ void fft2_fwd_kernel(const float* __restrict__ x) {
    extern __shared__ unsigned char s_raw[];
    float2* s = (float2*)s_raw;
    float2* tw = s + 128*FPITCH;
    int tid = threadIdx.x;  // 512
    int slice = blockIdx.x; // b*128 + c
    if (tid < 64) {
        float sv, cv; sincospif(-(float)tid * (1.0f/64.0f), &sv, &cv);
        tw[tid] = make_float2(cv, sv);
    }
    const float* xin = x + (size_t)slice * NHW;
    for (int idx = tid; idx < 16384; idx += 512) {
        int r = idx >> 7, c = idx & 127;
        s[r*FPITCH + c] = make_float2(xin[idx], 0.0f);
    }
    __syncthreads();
    fft2_128_r4<512>(s, tw, tid);
    float2* dst = d_xf + (size_t)slice * NHW;
    for (int idx = tid; idx < 16384; idx += 512) {
        int r = idx >> 7, c = idx & 127;
        dst[idx] = s[r*FPITCH + c];
    }
}

// ---------------- inverse FFT2 + abs of d_work -> d_outfl ----------------
__global__ void ifft2_abs_kernel() {
    extern __shared__ unsigned char s_raw[];
    float2* s = (float2*)s_raw;
    float2* tw = s + 128*FPITCH;
    int tid = threadIdx.x;  // 512
    int slice = blockIdx.x;
    if (tid < 64) {
        float sv, cv; sincospif((float)tid * (1.0f/64.0f), &sv, &cv);
        tw[tid] = make_float2(cv, sv);
    }
    const float2* xin = d_work + (size_t)slice * NHW;
    for (int idx = tid; idx < 16384; idx += 512) {
        int r = idx >> 7, c = idx & 127;
        s[r*FPITCH + c] = xin[idx];
    }
    __syncthreads();
    fft2_128_r4<512>(s, tw, tid);
    float* dst = d_outfl + (size_t)slice * NHW;
    const float sc = 1.0f / 16384.0f;
    for (int idx = tid; idx < 16384; idx += 512) {
        int r = idx >> 7, c = idx & 127;
        float2 v = s[r*FPITCH + c];
        dst[idx] = sqrtf(v.x*v.x + v.y*v.y) * sc;
    }
}

// ------- gram F partials: 128 threads, each computes (2cp,d) and (2cp+1,d) -------
__global__ void gram_f_part_kernel() {
    extern __shared__ unsigned char s_raw[];
    float2* sq = (float2*)s_raw;      // [16][514]
    int bh = blockIdx.x;              // b*8 + head
    int ns = blockIdx.y;              // n-chunk
    int tid = threadIdx.x;            // 128
    int cp = tid >> 4, d = tid & 15;  // c rows: 2cp, 2cp+1
    float2 acc0 = make_float2(0.f, 0.f), acc1 = make_float2(0.f, 0.f);
    float nrm0 = 0.f, nrm1 = 0.f;
    const float2* base = d_xf + (size_t)bh * HD * NHW + ns * (NHW / NS);
    for (int ch = 0; ch < NHW / NS; ch += 512) {
        for (int i = tid; i < 8192; i += 128) {
            int hh = i >> 9, j = i & 511;
            sq[hh*514 + j] = base[(size_t)hh*NHW + ch + j];
        }
        __syncthreads();
        #pragma unroll 4
        for (int j = 0; j < 512; j += 2) {
            float4 B  = *(const float4*)&sq[d*514 + j];
            float4 A0 = *(const float4*)&sq[(2*cp    )*514 + j];
            float4 A1 = *(const float4*)&sq[(2*cp + 1)*514 + j];
            acc0.x += A0.x*B.x - A0.y*B.y;
            acc0.y += A0.x*B.y + A0.y*B.x;
            acc0.x += A0.z*B.z - A0.w*B.w;
            acc0.y += A0.z*B.w + A0.w*B.z;
            acc1.x += A1.x*B.x - A1.y*B.y;
            acc1.y += A1.x*B.y + A1.y*B.x;
            acc1.x += A1.z*B.z - A1.w*B.w;
            acc1.y += A1.z*B.w + A1.w*B.z;
            if (d == 2*cp)     nrm0 += A0.x*A0.x + A0.y*A0.y + A0.z*A0.z + A0.w*A0.w;
            if (d == 2*cp + 1) nrm1 += A1.x*A1.x + A1.y*A1.y + A1.z*A1.z + A1.w*A1.w;
        }
        __syncthreads();
    }
    int part = bh * NS + ns;
    d_gfp[part*256 + (2*cp    )*16 + d] = acc0;
    d_gfp[part*256 + (2*cp + 1)*16 + d] = acc1;
    if (d == 2*cp)     d_gfn[part*16 + d] = nrm0;
    if (d == 2*cp + 1) d_gfn[part*16 + d] = nrm1;
}

// ---------------- gram F finalize ----------------
__global__ void attnf_finalize_kernel(const float* __restrict__ temp_f) {
    __shared__ float  snrm[16];
    __shared__ float2 sA[16][17];
    int bh = blockIdx.x;
    int tid = threadIdx.x;
    int c = tid >> 4, d = tid & 15;
    float2 acc = make_float2(0.f, 0.f);
    #pragma unroll
    for (int ns = 0; ns < NS; ++ns) {
        float2 p = d_gfp[(bh*NS + ns)*256 + tid];
        acc.x += p.x; acc.y += p.y;
    }
    if (tid < 16) {
        float nrm = 0.f;
        #pragma unroll
        for (int ns = 0; ns < NS; ++ns) nrm += d_gfn[(bh*NS + ns)*16 + tid];
        snrm[tid] = fmaxf(sqrtf(nrm), 1e-12f);
    }
    __syncthreads();
    float tf = temp_f[bh & 7];
    float inv = tf / (snrm[c] * snrm[d]);
    sA[c][d] = make_float2(acc.x * inv, acc.y * inv);
    __syncthreads();
    if (tid < 16) {
        int row = tid;
        float mr = -1e30f, mi = -1e30f;
        #pragma unroll
        for (int dd = 0; dd < 16; ++dd) {
            mr = fmaxf(mr, sA[row][dd].x);
            mi = fmaxf(mi, sA[row][dd].y);
        }
        float er[16], ei[16], sr = 0.f, si = 0.f;
        #pragma unroll
        for (int dd = 0; dd < 16; ++dd) {
            er[dd] = expf(sA[row][dd].x - mr);
            ei[dd] = expf(sA[row][dd].y - mi);
            sr += er[dd]; si += ei[dd];
        }
        float isr = 1.f/sr, isi = 1.f/si;
        #pragma unroll
        for (int dd = 0; dd < 16; ++dd)
            d_attnf[bh*256 + row*16 + dd] = make_float2(er[dd]*isr, ei[dd]*isi);
    }
}

// ------- out_cplx = attn_f @ qf, fused with IFFT-16 along hd (scalar R5 form) -------
__global__ void __launch_bounds__(256, 4) apply_attn_f_kernel() {
    __shared__ float2 A[256];
    int bh = blockIdx.x, nb = blockIdx.y;
    int tid = threadIdx.x;
    A[tid] = d_attnf[bh*256 + tid];
    __syncthreads();
    int n = nb*256 + tid;
    const float2* src = d_xf + (size_t)bh * HD * NHW + n;
    float2 o[16];
    #pragma unroll
    for (int cc = 0; cc < 16; ++cc) o[cc] = make_float2(0.f, 0.f);
    #pragma unroll
    for (int dd = 0; dd < 16; ++dd) {
        float2 qv = src[(size_t)dd * NHW];
        #pragma unroll
        for (int cc = 0; cc < 16; ++cc) {
            float2 a = A[cc*16 + dd];
            o[cc].x += a.x*qv.x - a.y*qv.y;
            o[cc].y += a.x*qv.y + a.y*qv.x;
        }
    }
    const int BR[16] = {0,8,4,12,2,10,6,14,1,9,5,13,3,11,7,15};
    float2 y[16];
    #pragma unroll
    for (int j = 0; j < 16; ++j) y[BR[j]] = o[j];
    const float C1 = 0.9238795325112867f, S1 = 0.3826834323650898f, R2 = 0.7071067811865476f;
    const float2 W[8] = {{1.f,0.f},{C1,S1},{R2,R2},{S1,C1},{0.f,1.f},{-S1,C1},{-R2,R2},{-C1,S1}};
    #pragma unroll
    for (int st = 0; st < 4; ++st) {
        int half = 1 << st;
        #pragma unroll
        for (int j = 0; j < 8; ++j) {
            int pos = j & (half - 1);
            int b2 = ((j >> st) << (st + 1)) + pos;
            float2 w = W[pos << (3 - st)];
            float2 a = y[b2];
            float2 t = cmul(y[b2 + half], w);
            y[b2]        = cadd(a, t);
            y[b2 + half] = csub(a, t);
        }
    }
    const float sc = 1.0f / 16.0f;
    float2* dst = d_work + (size_t)bh * HD * NHW + n;
    #pragma unroll
    for (int k = 0; k < 16; ++k)
        dst[(size_t)k * NHW] = make_float2(y[k].x*sc, y[k].y*sc);
}

// ---- 16384-point IFFT per row + abs -> d_outf (padded, table twiddles) ----
#define IX(i) ((i) + ((i) >> 5))
__global__ void ifft_row_kernel() {
    extern __shared__ unsigned char s_raw[];
    float2* dat = (float2*)s_raw;        // padded: 16896
    float2* tw  = dat + 16896;           // 8192
    __shared__ float2 hi[128], lo[64];
    int tid = threadIdx.x;               // 1024
    int row = blockIdx.x;                // b*128 + c
    if (tid < 128) {
        float sv, cv; sincospif((float)tid * (1.0f/128.0f), &sv, &cv);
        hi[tid] = make_float2(cv, sv);
    } else if (tid < 192) {
        int j = tid - 128;
        float sv, cv; sincospif((float)j * (1.0f/8192.0f), &sv, &cv);
        lo[j] = make_float2(cv, sv);
    }
    __syncthreads();
    for (int j = tid; j < 8192; j += 1024)
        tw[j] = cmul(hi[j >> 6], lo[j & 63]);
    const float2* src = d_work + (size_t)row * NHW;
    for (int j = tid; j < 16384; j += 1024) {
        int p = __brev(j) >> 18;
        dat[IX(p)] = src[j];
    }
    __syncthreads();
    #pragma unroll
    for (int st = 0; st < 14; st += 2) {
        int h = 1 << st;
        for (int idx = tid; idx < 4096; idx += 1024) {
            int pos = idx & (h - 1);
            int q = ((idx >> st) << (st + 2)) + pos;
            float2 a = dat[IX(q)], b = dat[IX(q+h)], c = dat[IX(q+2*h)], d = dat[IX(q+3*h)];
            float2 w1 = tw[pos << (13 - st)];
            float2 t  = cmul(b, w1);
            float2 u0 = cadd(a, t), u1 = csub(a, t);
            float2 t2 = cmul(d, w1);
            float2 u2 = cadd(c, t2), u3 = csub(c, t2);
            float2 w2 = tw[pos << (12 - st)];
            float2 w3 = tw[(pos + h) << (12 - st)];
            float2 v  = cmul(u2, w2);
            dat[IX(q)]     = cadd(u0, v);
            dat[IX(q+2*h)] = csub(u0, v);
            float2 v2 = cmul(u3, w3);
            dat[IX(q+h)]   = cadd(u1, v2);
            dat[IX(q+3*h)] = csub(u1, v2);
        }
        __syncthreads();
    }
    float* dst = d_outf + (size_t)row * NHW;
    const float sc = 1.0f / 16384.0f;
    for (int j = tid; j < 16384; j += 1024) {
        float2 v = dat[IX(j)];
        dst[j] = sqrtf(v.x*v.x + v.y*v.y) * sc;
    }
}

// ---------------- SE gate; d_work = g * xf (xf tile cached once) ----------------
__global__ void gate_kernel(const float* __restrict__ w1, const float* __restrict__ b1,
                            const float* __restrict__ bn_g, const float* __restrict__ bn_b,
                            const float* __restrict__ bn_m, const float* __restrict__ bn_v,
                            const float* __restrict__ w2, const float* __restrict__ b2) {
    extern __shared__ unsigned char s_raw[];
    float2* xc = (float2*)s_raw;              // [128][65]
    float* w1s = (float*)(xc + 128*65);       // [8][128]
    float* w2s = w1s + 1024;                  // [128][8]
    float* hid = w2s + 1024;                  // [8][65]
    int tid = threadIdx.x;
    int pp0 = blockIdx.x * 64;
    int b = pp0 >> 14, p0 = pp0 & (NHW-1);
    size_t sbase = (size_t)(b*128) * NHW + p0;
    for (int i = tid; i < 1024; i += 256) { w1s[i] = w1[i]; w2s[i] = w2[i]; }
    for (int i = tid; i < 8192; i += 256) {
        int cc = i >> 6, px = i & 63;
        xc[cc*65 + px] = d_xf[sbase + (size_t)cc * NHW + px];
    }
    __syncthreads();
    for (int t = tid; t < 512; t += 256) {
        int hc = t >> 6, px = t & 63;
        float h = b1[hc];
        #pragma unroll 8
        for (int cc = 0; cc < 128; ++cc) h += w1s[hc*128 + cc] * xc[cc*65 + px].x;
        h = (h - bn_m[hc]) * rsqrtf(bn_v[hc] + 1e-5f) * bn_g[hc] + bn_b[hc];
        hid[hc*65 + px] = fmaxf(h, 0.0f);
    }
    __syncthreads();
    for (int t = tid; t < 8192; t += 256) {
        int oc = t >> 6, px = t & 63;
        float sv = b2[oc];
        #pragma unroll
        for (int hc = 0; hc < 8; ++hc) sv += w2s[oc*8 + hc] * hid[hc*65 + px];
        float gg = 1.0f / (1.0f + expf(-sv));
        float2 xv = xc[oc*65 + px];
        d_work[sbase + (size_t)oc * NHW + px] = make_float2(gg*xv.x, gg*xv.y);
    }
}

// ---------------- 1x1 conv (128->128, bias), FFMA2 packed over oc pairs ----------------
__global__ void conv1x1_kernel(const float* __restrict__ in, const float* __restrict__ w,
                               const float* __restrict__ bias, float* __restrict__ out) {
    extern __shared__ unsigned char s_raw[];
    float* wt = (float*)s_raw;        // [128 ic][134]  (oc fast, transposed)
    float* xs = wt + 128*134;         // [128 ic][68]
    int tid = threadIdx.x;
    int pp0 = blockIdx.x * 64;
    int b = pp0 >> 14, p0 = pp0 & (NHW-1);
    for (int i = tid; i < 16384; i += 256) {
        int oc = i >> 7, ic = i & 127;
        wt[ic*134 + oc] = w[i];
    }
    for (int i = tid; i < 8192; i += 256) {
        int cc = i >> 6, px = i & 63;
        xs[cc*68 + px] = in[(size_t)(b*128 + cc) * NHW + p0 + px];
    }
    __syncthreads();
    int ocg = tid >> 4, pxg = tid & 15;
    int ocb = ocg * 8;
    unsigned long long acc2[4][4];
    #pragma unroll
    for (int p = 0; p < 4; ++p) {
        unsigned long long bp = pk2(bias[ocb + 2*p], bias[ocb + 2*p + 1]);
        #pragma unroll
        for (int v = 0; v < 4; ++v) acc2[p][v] = bp;
    }
    #pragma unroll 4
    for (int i = 0; i < 128; ++i) {
        float4 xv = *(const float4*)&xs[i*68 + pxg*4];
        unsigned long long xd0 = pk2(xv.x, xv.x);
        unsigned long long xd1 = pk2(xv.y, xv.y);
        unsigned long long xd2 = pk2(xv.z, xv.z);
        unsigned long long xd3 = pk2(xv.w, xv.w);
        const float* wrow = &wt[i*134 + ocb];
        #pragma unroll
        for (int p = 0; p < 4; ++p) {
            unsigned long long w2 = *(const unsigned long long*)&wrow[2*p];
            ffma2(acc2[p][0], w2, xd0);
            ffma2(acc2[p][1], w2, xd1);
            ffma2(acc2[p][2], w2, xd2);
            ffma2(acc2[p][3], w2, xd3);
        }
    }
    #pragma unroll
    for (int p = 0; p < 4; ++p) {
        float2 a0 = upk2(acc2[p][0]), a1 = upk2(acc2[p][1]);
        float2 a2 = upk2(acc2[p][2]), a3 = upk2(acc2[p][3]);
        int oc = ocb + 2*p;
        *(float4*)&out[(size_t)(b*128 + oc    ) * NHW + p0 + pxg*4] = make_float4(a0.x, a1.x, a2.x, a3.x);
        *(float4*)&out[(size_t)(b*128 + oc + 1) * NHW + p0 + pxg*4] = make_float4(a0.y, a1.y, a2.y, a3.y);
    }
}

// ------- grouped conv3 + conv5 (concat): 32x32 tile, FFMA2, packed weights -------
__global__ void gconv_kernel(const float* __restrict__ in, const float* __restrict__ w3,
                             const float* __restrict__ w5, float* __restrict__ out) {
    __shared__ float t0[36*40], t1[36*40];             // halo tiles, pitch 40 (16B aligned rows)
    __shared__ unsigned long long wp3[2][9], wp5[2][25]; // packed (w,w)
    int tid = threadIdx.x;
    int tile = blockIdx.x, g = blockIdx.y, b = blockIdx.z;
    int ty0 = (tile >> 2) * 32, tx0 = (tile & 3) * 32;
    const float* in0 = in + (size_t)(b*128 + 2*g) * NHW;
    const float* in1 = in0 + NHW;
    for (int i = tid; i < 1296; i += 256) {
        int ly = i / 36, lx = i % 36;
        int gy = ty0 - 2 + ly, gx = tx0 - 2 + lx;
        bool ok = ((unsigned)gy < 128u) && ((unsigned)gx < 128u);
        t0[ly*40 + lx] = ok ? in0[gy*128 + gx] : 0.f;
        t1[ly*40 + lx] = ok ? in1[gy*128 + gx] : 0.f;
    }
    if (tid < 18) {
        int ch = tid / 9, k = tid % 9;
        float w = w3[(g*2 + ch)*9 + k];
        wp3[ch][k] = pk2(w, w);
    } else if (tid >= 32 && tid < 82) {
        int t2 = tid - 32;
        int ch = t2 / 25, k = t2 % 25;
        float w = w5[(g*2 + ch)*25 + k];
        wp5[ch][k] = pk2(w, w);
    }
    __syncthreads();
    int ty = tid >> 3;             // 0..31
    int tx = (tid & 7) * 4;        // 0,4,...,28
    unsigned long long a3q0 = 0ULL, a3q1 = 0ULL, a5q0 = 0ULL, a5q1 = 0ULL;
    #pragma unroll
    for (int ch = 0; ch < 2; ++ch) {
        const float* t = ch ? t1 : t0;
        #pragma unroll
        for (int ky = 0; ky < 5; ++ky) {
            const float* row = &t[(ty + ky)*40 + tx];
            float4 rA = *(const float4*)row;
            float4 rB = *(const float4*)(row + 4);
            float r0 = rA.x, r1 = rA.y, r2 = rA.z, r3 = rA.w;
            float r4 = rB.x, r5 = rB.y, r6 = rB.z, r7 = rB.w;
            unsigned long long p0 = pk2(r0, r1), p1 = pk2(r1, r2), p2 = pk2(r2, r3);
            unsigned long long p3 = pk2(r3, r4), p4 = pk2(r4, r5), p5 = pk2(r5, r6);
            unsigned long long p6 = pk2(r6, r7);
            unsigned long long pr[7] = { p0, p1, p2, p3, p4, p5, p6 };
            #pragma unroll
            for (int kx = 0; kx < 5; ++kx) {
                unsigned long long w = wp5[ch][ky*5 + kx];
                ffma2(a5q0, w, pr[kx]);
                ffma2(a5q1, w, pr[kx + 2]);
            }
            if (ky >= 1 && ky <= 3) {
                #pragma unroll
                for (int kx = 0; kx < 3; ++kx) {
                    unsigned long long w = wp3[ch][(ky - 1)*3 + kx];
                    ffma2(a3q0, w, pr[1 + kx]);
                    ffma2(a3q1, w, pr[3 + kx]);
                }
            }
        }
    }
    int py = ty0 + ty, px = tx0 + tx;
    float2 a30 = upk2(a3q0), a31 = upk2(a3q1);
    float2 a50 = upk2(a5q0), a51 = upk2(a5q1);
    *(float4*)&out[(size_t)(b*128 + g)      * NHW + py*128 + px] = make_float4(a30.x, a30.y, a31.x, a31.y);
    *(float4*)&out[(size_t)(b*128 + 64 + g) * NHW + py*128 + px] = make_float4(a50.x, a50.y, a51.x, a51.y);
}

// ------- gram S partials: 128 threads, each computes (2cp,d) and (2cp+1,d) -------
__global__ void gram_s_part_kernel() {
    extern __shared__ unsigned char s_raw[];
    float* sq = (float*)s_raw;           // [16][516]
    float* sk = sq + 16*516;             // [16][516]
    int bh = blockIdx.x;
    int ns = blockIdx.y;
    int tid = threadIdx.x;               // 128
    int cp = tid >> 4, d = tid & 15;
    const float* qb = d_q + (size_t)bh * HD * NHW + ns * (NHW / NS);
    const float* kb = d_k + (size_t)bh * HD * NHW + ns * (NHW / NS);
    float acc0 = 0.f, acc1 = 0.f, nq0 = 0.f, nq1 = 0.f, nk = 0.f;
    for (int ch = 0; ch < NHW / NS; ch += 512) {
        for (int i = tid; i < 8192; i += 128) {
            int hh = i >> 9, j = i & 511;
            sq[hh*516 + j] = qb[(size_t)hh*NHW + ch + j];
            sk[hh*516 + j] = kb[(size_t)hh*NHW + ch + j];
        }
        __syncthreads();
        #pragma unroll 4
        for (int j = 0; j < 512; j += 4) {
            float4 B  = *(const float4*)&sk[d*516 + j];
            float4 A0 = *(const float4*)&sq[(2*cp    )*516 + j];
            float4 A1 = *(const float4*)&sq[(2*cp + 1)*516 + j];
            acc0 += A0.x*B.x + A0.y*B.y + A0.z*B.z + A0.w*B.w;
            acc1 += A1.x*B.x + A1.y*B.y + A1.z*B.z + A1.w*B.w;
            if (d == 2*cp) {
                nq0 += A0.x*A0.x + A0.y*A0.y + A0.z*A0.z + A0.w*A0.w;
                nk  += B.x*B.x + B.y*B.y + B.z*B.z + B.w*B.w;
            } else if (d == 2*cp + 1) {
                nq1 += A1.x*A1.x + A1.y*A1.y + A1.z*A1.z + A1.w*A1.w;
                nk  += B.x*B.x + B.y*B.y + B.z*B.z + B.w*B.w;
            }
        }
        __syncthreads();
    }
    int part = bh * NS + ns;
    d_gsp[part*256 + (2*cp    )*16 + d] = acc0;
    d_gsp[part*256 + (2*cp + 1)*16 + d] = acc1;
    if (d == 2*cp)      { d_gsq[part*16 + d] = nq0; d_gsk[part*16 + d] = nk; }
    else if (d == 2*cp + 1) { d_gsq[part*16 + d] = nq1; d_gsk[part*16 + d] = nk; }
}

// ---------------- gram S finalize ----------------
__global__ void attns_finalize_kernel(const float* __restrict__ temp_s) {
    __shared__ float snq[16], snk[16];
    __shared__ float sA[16][17];
    int bh = blockIdx.x;
    int tid = threadIdx.x;
    int c = tid >> 4, d = tid & 15;
    float acc = 0.f;
    #pragma unroll
    for (int ns = 0; ns < NS; ++ns) acc += d_gsp[(bh*NS + ns)*256 + tid];
    if (tid < 16) {
        float nq = 0.f, nk = 0.f;
        #pragma unroll
        for (int ns = 0; ns < NS; ++ns) {
            nq += d_gsq[(bh*NS + ns)*16 + tid];
            nk += d_gsk[(bh*NS + ns)*16 + tid];
        }
        snq[tid] = fmaxf(sqrtf(nq), 1e-12f);
        snk[tid] = fmaxf(sqrtf(nk), 1e-12f);
    }
    __syncthreads();
    sA[c][d] = acc * temp_s[bh & 7] / (snq[c] * snk[d]);
    __syncthreads();
    if (tid < 16) {
        int row = tid;
        float m = -1e30f;
        #pragma unroll
        for (int dd = 0; dd < 16; ++dd) m = fmaxf(m, sA[row][dd]);
        float e[16], s = 0.f;
        #pragma unroll
        for (int dd = 0; dd < 16; ++dd) { e[dd] = expf(sA[row][dd] - m); s += e[dd]; }
        float is = 1.f / s;
        #pragma unroll
        for (int dd = 0; dd < 16; ++dd) d_attns[bh*256 + row*16 + dd] = e[dd] * is;
    }
}

// ---------------- out_s = attn_s @ v -> d_bufT (FFMA2 over cc pairs) ----------------
__global__ void __launch_bounds__(256, 4) apply_attn_s_kernel() {
    __shared__ ulonglong2 At[64];   // [dd][pq]: pq covers cc pairs (4pq..4pq+3)
    int bh = blockIdx.x, nb = blockIdx.y;
    int tid = threadIdx.x;
    if (tid < 64) {
        int dd = tid >> 2, pq = tid & 3;
        const float* Ab = d_attns + bh*256;
        At[tid] = make_ulonglong2(
            pk2(Ab[(4*pq    )*16 + dd], Ab[(4*pq + 1)*16 + dd]),
            pk2(Ab[(4*pq + 2)*16 + dd], Ab[(4*pq + 3)*16 + dd]));
    }
    __syncthreads();
    int n = nb*256 + tid;
    const float* vb = d_v + (size_t)bh * HD * NHW + n;
    unsigned long long o2[8];
    #pragma unroll
    for (int p = 0; p < 8; ++p) o2[p] = 0ULL;
    #pragma unroll
    for (int dd = 0; dd < 16; ++dd) {
        float vv = vb[(size_t)dd * NHW];
        unsigned long long vd = pk2(vv, vv);
        #pragma unroll
        for (int pq = 0; pq < 4; ++pq) {
            ulonglong2 ap = At[dd*4 + pq];
            ffma2(o2[pq*2    ], ap.x, vd);
            ffma2(o2[pq*2 + 1], ap.y, vd);
        }
    }
    float* dst = d_bufT + (size_t)bh * HD * NHW + n;
    #pragma unroll
    for (int p = 0; p < 8; ++p) {
        float2 o = upk2(o2[p]);
        dst[(size_t)(2*p    ) * NHW] = o.x;
        dst[(size_t)(2*p + 1) * NHW] = o.y;
    }
}

// ---------------- final fused projection (fsa + ssa), FFMA2 ----------------
__global__ void final_conv_kernel(const float* __restrict__ pfw, const float* __restrict__ psw,
                                  float* __restrict__ out) {
    extern __shared__ unsigned char s_raw[];
    float* wt = (float*)s_raw;        // [128 ic][134]
    float* xs = wt + 128*134;         // [128 ic][68]
    int tid = threadIdx.x;
    int pp0 = blockIdx.x * 64;
    int b = pp0 >> 14, p0 = pp0 & (NHW-1);
    int ocg = tid >> 4, pxg = tid & 15;
    int ocb = ocg * 8;
    unsigned long long acc2[4][4];
    #pragma unroll
    for (int p = 0; p < 4; ++p)
        #pragma unroll
        for (int v = 0; v < 4; ++v) acc2[p][v] = 0ULL;
    const float* ins[4] = { d_outf, d_outfl, d_bufT, d_outsl };
    for (int pass = 0; pass < 4; ++pass) {
        const float* wsrc = (pass < 2) ? pfw : psw;
        int off = (pass & 1) * 128;
        for (int i = tid; i < 16384; i += 256) {
            int oc = i >> 7, ic = i & 127;
            wt[ic*134 + oc] = wsrc[oc*256 + off + ic];
        }
        const float* in = ins[pass];
        for (int i = tid; i < 8192; i += 256) {
            int cc = i >> 6, px = i & 63;
            xs[cc*68 + px] = in[(size_t)(b*128 + cc) * NHW + p0 + px];
        }
        __syncthreads();
        #pragma unroll 4
        for (int i = 0; i < 128; ++i) {
            float4 xv = *(const float4*)&xs[i*68 + pxg*4];
            unsigned long long xd0 = pk2(xv.x, xv.x);
            unsigned long long xd1 = pk2(xv.y, xv.y);
            unsigned long long xd2 = pk2(xv.z, xv.z);
            unsigned long long xd3 = pk2(xv.w, xv.w);
            const float* wrow = &wt[i*134 + ocb];
            #pragma unroll
            for (int p = 0; p < 4; ++p) {
                unsigned long long w2 = *(const unsigned long long*)&wrow[2*p];
                ffma2(acc2[p][0], w2, xd0);
                ffma2(acc2[p][1], w2, xd1);
                ffma2(acc2[p][2], w2, xd2);
                ffma2(acc2[p][3], w2, xd3);
            }
        }
        __syncthreads();
    }
    #pragma unroll
    for (int p = 0; p < 4; ++p) {
        float2 a0 = upk2(acc2[p][0]), a1 = upk2(acc2[p][1]);
        float2 a2 = upk2(acc2[p][2]), a3 = upk2(acc2[p][3]);
        int oc = ocb + 2*p;
        *(float4*)&out[(size_t)(b*128 + oc    ) * NHW + p0 + pxg*4] = make_float4(a0.x, a1.x, a2.x, a3.x);
        *(float4*)&out[(size_t)(b*128 + oc + 1) * NHW + p0 + pxg*4] = make_float4(a0.y, a1.y, a2.y, a3.y);
    }
}

// ---------------- host launcher ----------------
#define SM_FFT2  ((128*FPITCH + 64) * (int)sizeof(float2))      // 132,608
#define SM_ROW   ((16896 + 8192) * (int)sizeof(float2))         // 200,704
#define SM_GRAMF (16*514 * (int)sizeof(float2))                 //  65,792
#define SM_GRAMS (2*16*516 * (int)sizeof(float))                //  66,048
#define SM_CONV  ((128*134 + 128*68) * (int)sizeof(float))      // 103,424
#define SM_GATE  ((128*65) * (int)sizeof(float2) + (1024 + 1024 + 8*65) * (int)sizeof(float))

extern "C" void kernel_launch(void* const* d_in, const int* in_sizes, int n_in,
                              void* d_out, int out_size) {
    (void)in_sizes; (void)n_in; (void)out_size;
    const float* x       = (const float*)d_in[0];
    const float* temp_f  = (const float*)d_in[1];
    const float* w1      = (const float*)d_in[2];
    const float* b1      = (const float*)d_in[3];
    const float* bn_g    = (const float*)d_in[4];
    const float* bn_b    = (const float*)d_in[5];
    const float* bn_m    = (const float*)d_in[6];
    const float* bn_v    = (const float*)d_in[7];
    const float* w2      = (const float*)d_in[8];
    const float* b2      = (const float*)d_in[9];
    const float* projf_w = (const float*)d_in[10];
    const float* temp_s  = (const float*)d_in[11];
    const float* q1_w = (const float*)d_in[12];
    const float* q1_b = (const float*)d_in[13];
    const float* k1_w = (const float*)d_in[14];
    const float* k1_b = (const float*)d_in[15];
    const float* v1_w = (const float*)d_in[16];
    const float* v1_b = (const float*)d_in[17];
    const float* q3_w = (const float*)d_in[18];
    const float* q5_w = (const float*)d_in[19];
    const float* k3_w = (const float*)d_in[20];
    const float* k5_w = (const float*)d_in[21];
    const float* v3_w = (const float*)d_in[22];
    const float* v5_w = (const float*)d_in[23];
    const float* c3_w = (const float*)d_in[24];
    const float* c5_w = (const float*)d_in[25];
    const float* projs_w = (const float*)d_in[26];
    float* out = (float*)d_out;

    cudaFuncSetAttribute(fft2_fwd_kernel,    cudaFuncAttributeMaxDynamicSharedMemorySize, SM_FFT2);
    cudaFuncSetAttribute(ifft2_abs_kernel,   cudaFuncAttributeMaxDynamicSharedMemorySize, SM_FFT2);
    cudaFuncSetAttribute(ifft_row_kernel,    cudaFuncAttributeMaxDynamicSharedMemorySize, SM_ROW);
    cudaFuncSetAttribute(gram_f_part_kernel, cudaFuncAttributeMaxDynamicSharedMemorySize, SM_GRAMF);
    cudaFuncSetAttribute(gram_s_part_kernel, cudaFuncAttributeMaxDynamicSharedMemorySize, SM_GRAMS);
    cudaFuncSetAttribute(conv1x1_kernel,     cudaFuncAttributeMaxDynamicSharedMemorySize, SM_CONV);
    cudaFuncSetAttribute(final_conv_kernel,  cudaFuncAttributeMaxDynamicSharedMemorySize, SM_CONV);
    cudaFuncSetAttribute(gate_kernel,        cudaFuncAttributeMaxDynamicSharedMemorySize, SM_GATE);

    float *pT, *pQ, *pK, *pV, *pSL, *pW;
    cudaGetSymbolAddress((void**)&pT,  d_bufT);
    cudaGetSymbolAddress((void**)&pQ,  d_q);
    cudaGetSymbolAddress((void**)&pK,  d_k);
    cudaGetSymbolAddress((void**)&pV,  d_v);
    cudaGetSymbolAddress((void**)&pSL, d_outsl);
    cudaGetSymbolAddress((void**)&pW,  d_work);
    // qkv temps: tq/tk overlay d_work (float2 = 2x float), tv = d_bufT.
    float* tq = pW;
    float* tk = pW + NELEM;
    float* tv = pT;

    // ---- frequency branch ----
    fft2_fwd_kernel<<<1024, 512, SM_FFT2>>>(x);
    gram_f_part_kernel<<<dim3(64, NS), 128, SM_GRAMF>>>();
    attnf_finalize_kernel<<<64, 256>>>(temp_f);
    apply_attn_f_kernel<<<dim3(64, 64), 256>>>();   // fused with ifft16
    ifft_row_kernel<<<1024, 1024, SM_ROW>>>();
    gate_kernel<<<2048, 256, SM_GATE>>>(w1, b1, bn_g, bn_b, bn_m, bn_v, w2, b2);
    ifft2_abs_kernel<<<1024, 512, SM_FFT2>>>();

    // ---- spatial branch ----
    conv1x1_kernel<<<2048, 256, SM_CONV>>>(x, q1_w, q1_b, tq);
    gconv_kernel<<<dim3(16, 64, 8), 256>>>(tq, q3_w, q5_w, pQ);
    conv1x1_kernel<<<2048, 256, SM_CONV>>>(x, k1_w, k1_b, tk);
    gconv_kernel<<<dim3(16, 64, 8), 256>>>(tk, k3_w, k5_w, pK);
    conv1x1_kernel<<<2048, 256, SM_CONV>>>(x, v1_w, v1_b, tv);
    gconv_kernel<<<dim3(16, 64, 8), 256>>>(tv, v3_w, v5_w, pV);
    gconv_kernel<<<dim3(16, 64, 8), 256>>>(x, c3_w, c5_w, pSL);
    gram_s_part_kernel<<<dim3(64, NS), 128, SM_GRAMS>>>();
    attns_finalize_kernel<<<64, 256>>>(temp_s);
    apply_attn_s_kernel<<<dim3(64, 64), 256>>>();   // writes d_bufT (out_s)

    // ---- fused projections + sum ----
    final_conv_kernel<<<2048, 256, SM_CONV>>>(projf_w, projs_w, out);
}

// round 13
// speedup vs baseline: 1.1587x; 1.1587x over previous
#include <cuda_runtime.h>
#include <cstdint>

// ---------------- problem constants ----------------
#define NB     8
#define NC     128
#define NHW    16384            // 128*128
#define NHEADS 8
#define HD     16               // head dim (channels per head)
#define NELEM  16777216         // NB*NC*NHW
#define NS     16               // gram n-split

#define FPITCH 129              // 128x128 fft tile pitch (float2)

// ---------------- scratch (device globals; no allocs allowed) ----------------
__device__ float2 d_xf[NELEM];      // fft2(x)
__device__ float2 d_work[NELEM];    // out_cplx(post ifft16) / g*xf  (freq branch ONLY)
__device__ float  d_outf[NELEM];    // |ifft2(out_cplx)|
__device__ float  d_outfl[NELEM];   // |ifft2(g*xf)|
__device__ float  d_q[NELEM];
__device__ float  d_k[NELEM];
__device__ float  d_v[NELEM];
__device__ float  d_outsl[NELEM];
__device__ float  d_bufT[NELEM];    // v-temp, then out_s (spatial branch)
__device__ float  d_tq[NELEM];      // q-temp (spatial branch)
__device__ float  d_tk[NELEM];      // k-temp (spatial branch)
__device__ float2 d_attnf[NB*NHEADS*HD*HD];
__device__ float  d_attns[NB*NHEADS*HD*HD];
// gram partials
__device__ float2 d_gfp[NB*NHEADS*NS*256];
__device__ float  d_gfn[NB*NHEADS*NS*16];
__device__ float  d_gsp[NB*NHEADS*NS*256];
__device__ float  d_gsq[NB*NHEADS*NS*16];
__device__ float  d_gsk[NB*NHEADS*NS*16];

// ---------------- helpers ----------------
__device__ __forceinline__ float2 cmul(float2 a, float2 b) {
    return make_float2(a.x*b.x - a.y*b.y, a.x*b.y + a.y*b.x);
}
__device__ __forceinline__ float2 cadd(float2 a, float2 b) { return make_float2(a.x+b.x, a.y+b.y); }
__device__ __forceinline__ float2 csub(float2 a, float2 b) { return make_float2(a.x-b.x, a.y-b.y); }
__device__ __forceinline__ int brev7(int v) { return __brev(v) >> 25; }

// ---- packed fp32x2 (Blackwell FFMA2 path) ----
__device__ __forceinline__ unsigned long long pk2(float a, float b) {
    unsigned long long r;
    asm("mov.b64 %0, {%1, %2};" : "=l"(r) : "f"(a), "f"(b));
    return r;
}
__device__ __forceinline__ void ffma2(unsigned long long& c, unsigned long long a, unsigned long long b) {
    asm("fma.rn.f32x2 %0, %1, %2, %0;" : "+l"(c) : "l"(a), "l"(b));
}
__device__ __forceinline__ float2 upk2(unsigned long long v) {
    float2 r;
    asm("mov.b64 {%0, %1}, %2;" : "=f"(r.x), "=f"(r.y) : "l"(v));
    return r;
}

// ============ 2D 128x128 FFT (radix-2^2), input loaded bit-reversed ============
// tw[j] = exp(dir*i*pi*j/64), j in [0,64). NT = threads.
// Column stages are ROW-FAST so LDS/STS are conflict-free.
template <int NT>
__device__ void fft2_128_r4(float2* s, const float2* tw, int tid) {
    #pragma unroll
    for (int st = 0; st < 6; st += 2) {
        int h = 1 << st;
        for (int idx = tid; idx < 4096; idx += NT) {
            int r = idx & 127, j = idx >> 7;      // j in [0,32)
            int pos = j & (h - 1);
            int q = ((j >> st) << (st + 2)) + pos;
            float2* row = s + r * FPITCH;
            float2 a = row[q], b = row[q+h], c = row[q+2*h], d = row[q+3*h];
            float2 w1 = tw[pos << (6 - st)];
            float2 t  = cmul(b, w1);
            float2 u0 = cadd(a, t), u1 = csub(a, t);
            float2 t2 = cmul(d, w1);
            float2 u2 = cadd(c, t2), u3 = csub(c, t2);
            float2 w2 = tw[pos << (5 - st)];
            float2 w3 = tw[(pos + h) << (5 - st)];
            float2 v  = cmul(u2, w2);
            row[q]       = cadd(u0, v);
            row[q+2*h]   = csub(u0, v);
            float2 v2 = cmul(u3, w3);
            row[q+h]     = cadd(u1, v2);
            row[q+3*h]   = csub(u1, v2);
        }
        __syncthreads();
    }
    for (int idx = tid; idx < 8192; idx += NT) {
        int r = idx & 127, pos = idx >> 7;        // pos in [0,64)
        float2 w = tw[pos];
        float2* p0 = &s[r*FPITCH + pos];
        float2* p1 = &s[r*FPITCH + pos + 64];
        float2 a = *p0, t = cmul(*p1, w);
        *p0 = cadd(a, t);
        *p1 = csub(a, t);
    }
    __syncthreads();
    #pragma unroll
    for (int st = 0; st < 6; st += 2) {
        int h = 1 << st;
        for (int idx = tid; idx < 4096; idx += NT) {
            int c0 = idx & 127, j = idx >> 7;
            int pos = j & (h - 1);
            int q = ((j >> st) << (st + 2)) + pos;
            float2 a = s[(q      )*FPITCH + c0];
            float2 b = s[(q +   h)*FPITCH + c0];
            float2 c = s[(q + 2*h)*FPITCH + c0];
            float2 d = s[(q + 3*h)*FPITCH + c0];
            float2 w1 = tw[pos << (6 - st)];
            float2 t  = cmul(b, w1);
            float2 u0 = cadd(a, t), u1 = csub(a, t);
            float2 t2 = cmul(d, w1);
            float2 u2 = cadd(c, t2), u3 = csub(c, t2);
            float2 w2 = tw[pos << (5 - st)];
            float2 w3 = tw[(pos + h) << (5 - st)];
            float2 v  = cmul(u2, w2);
            s[(q      )*FPITCH + c0] = cadd(u0, v);
            s[(q + 2*h)*FPITCH + c0] = csub(u0, v);
            float2 v2 = cmul(u3, w3);
            s[(q +   h)*FPITCH + c0] = cadd(u1, v2);
            s[(q + 3*h)*FPITCH + c0] = csub(u1, v2);
        }
        __syncthreads();
    }
    for (int idx = tid; idx < 8192; idx += NT) {
        int c0 = idx & 127, pos = idx >> 7;
        float2 w = tw[pos];
        float2* p0 = &s[pos*FPITCH + c0];
        float2* p1 = &s[(pos + 64)*FPITCH + c0];
        float2 a = *p0, t = cmul(*p1, w);
        *p0 = cadd(a, t);
        *p1 = csub(a, t);
    }
    __syncthreads();
}

// ---------------- forward FFT2 of x -> d_xf ----------------
__global__ void fft2_fwd_kernel(const float* __restrict__ x) {
    extern __shared__ unsigned char s_raw[];
    float2* s = (float2*)s_raw;
    float2* tw = s + 128*FPITCH;
    int tid = threadIdx.x;  // 512
    int slice = blockIdx.x; // b*128 + c
    if (tid < 64) {
        float sv, cv; sincospif(-(float)tid * (1.0f/64.0f), &sv, &cv);
        tw[tid] = make_float2(cv, sv);
    }
    const float* xin = x + (size_t)slice * NHW;
    for (int idx = tid; idx < 16384; idx += 512) {
        int r = idx >> 7, c = idx & 127;
        s[brev7(r)*FPITCH + brev7(c)] = make_float2(xin[idx], 0.0f);
    }
    __syncthreads();
    fft2_128_r4<512>(s, tw, tid);
    float2* dst = d_xf + (size_t)slice * NHW;
    for (int idx = tid; idx < 16384; idx += 512) {
        int r = idx >> 7, c = idx & 127;
        dst[idx] = s[r*FPITCH + c];
    }
}

// ---------------- inverse FFT2 + abs of d_work -> d_outfl ----------------
__global__ void ifft2_abs_kernel() {
    extern __shared__ unsigned char s_raw[];
    float2* s = (float2*)s_raw;
    float2* tw = s + 128*FPITCH;
    int tid = threadIdx.x;  // 512
    int slice = blockIdx.x;
    if (tid < 64) {
        float sv, cv; sincospif((float)tid * (1.0f/64.0f), &sv, &cv);
        tw[tid] = make_float2(cv, sv);
    }
    const float2* xin = d_work + (size_t)slice * NHW;
    for (int idx = tid; idx < 16384; idx += 512) {
        int r = idx >> 7, c = idx & 127;
        s[brev7(r)*FPITCH + brev7(c)] = xin[idx];
    }
    __syncthreads();
    fft2_128_r4<512>(s, tw, tid);
    float* dst = d_outfl + (size_t)slice * NHW;
    const float sc = 1.0f / 16384.0f;
    for (int idx = tid; idx < 16384; idx += 512) {
        int r = idx >> 7, c = idx & 127;
        float2 v = s[r*FPITCH + c];
        dst[idx] = sqrtf(v.x*v.x + v.y*v.y) * sc;
    }
}

// ---------------- gram F partials (float4 loads, pitch 514) ----------------
__global__ void gram_f_part_kernel() {
    extern __shared__ unsigned char s_raw[];
    float2* sq = (float2*)s_raw;      // [16][514]
    int bh = blockIdx.x;              // b*8 + head
    int ns = blockIdx.y;              // n-chunk
    int tid = threadIdx.x;
    int c = tid >> 4, d = tid & 15;
    float2 acc = make_float2(0.f, 0.f);
    float nrm = 0.f;
    const float2* base = d_xf + (size_t)bh * HD * NHW + ns * (NHW / NS);
    for (int ch = 0; ch < NHW / NS; ch += 512) {
        for (int i = tid; i < 8192; i += 256) {
            int hh = i >> 9, j = i & 511;
            sq[hh*514 + j] = base[(size_t)hh*NHW + ch + j];
        }
        __syncthreads();
        #pragma unroll 4
        for (int j = 0; j < 512; j += 2) {
            float4 A = *(const float4*)&sq[c*514 + j];
            float4 B = *(const float4*)&sq[d*514 + j];
            acc.x += A.x*B.x - A.y*B.y;
            acc.y += A.x*B.y + A.y*B.x;
            acc.x += A.z*B.z - A.w*B.w;
            acc.y += A.z*B.w + A.w*B.z;
            if (c == d) nrm += A.x*A.x + A.y*A.y + A.z*A.z + A.w*A.w;
        }
        __syncthreads();
    }
    int part = bh * NS + ns;
    d_gfp[part*256 + tid] = acc;
    if (c == d) d_gfn[part*16 + c] = nrm;
}

// ---------------- gram F finalize ----------------
__global__ void attnf_finalize_kernel(const float* __restrict__ temp_f) {
    __shared__ float  snrm[16];
    __shared__ float2 sA[16][17];
    int bh = blockIdx.x;
    int tid = threadIdx.x;
    int c = tid >> 4, d = tid & 15;
    float2 acc = make_float2(0.f, 0.f);
    #pragma unroll
    for (int ns = 0; ns < NS; ++ns) {
        float2 p = d_gfp[(bh*NS + ns)*256 + tid];
        acc.x += p.x; acc.y += p.y;
    }
    if (tid < 16) {
        float nrm = 0.f;
        #pragma unroll
        for (int ns = 0; ns < NS; ++ns) nrm += d_gfn[(bh*NS + ns)*16 + tid];
        snrm[tid] = fmaxf(sqrtf(nrm), 1e-12f);
    }
    __syncthreads();
    float tf = temp_f[bh & 7];
    float inv = tf / (snrm[c] * snrm[d]);
    sA[c][d] = make_float2(acc.x * inv, acc.y * inv);
    __syncthreads();
    if (tid < 16) {
        int row = tid;
        float mr = -1e30f, mi = -1e30f;
        #pragma unroll
        for (int dd = 0; dd < 16; ++dd) {
            mr = fmaxf(mr, sA[row][dd].x);
            mi = fmaxf(mi, sA[row][dd].y);
        }
        float er[16], ei[16], sr = 0.f, si = 0.f;
        #pragma unroll
        for (int dd = 0; dd < 16; ++dd) {
            er[dd] = expf(sA[row][dd].x - mr);
            ei[dd] = expf(sA[row][dd].y - mi);
            sr += er[dd]; si += ei[dd];
        }
        float isr = 1.f/sr, isi = 1.f/si;
        #pragma unroll
        for (int dd = 0; dd < 16; ++dd)
            d_attnf[bh*256 + row*16 + dd] = make_float2(er[dd]*isr, ei[dd]*isi);
    }
}

// ------- out_cplx = attn_f @ qf, fused with IFFT-16 along hd (scalar R5 form) -------
__global__ void __launch_bounds__(256, 4) apply_attn_f_kernel() {
    __shared__ float2 A[256];
    int bh = blockIdx.x, nb = blockIdx.y;
    int tid = threadIdx.x;
    A[tid] = d_attnf[bh*256 + tid];
    __syncthreads();
    int n = nb*256 + tid;
    const float2* src = d_xf + (size_t)bh * HD * NHW + n;
    float2 o[16];
    #pragma unroll
    for (int cc = 0; cc < 16; ++cc) o[cc] = make_float2(0.f, 0.f);
    #pragma unroll
    for (int dd = 0; dd < 16; ++dd) {
        float2 qv = src[(size_t)dd * NHW];
        #pragma unroll
        for (int cc = 0; cc < 16; ++cc) {
            float2 a = A[cc*16 + dd];
            o[cc].x += a.x*qv.x - a.y*qv.y;
            o[cc].y += a.x*qv.y + a.y*qv.x;
        }
    }
    const int BR[16] = {0,8,4,12,2,10,6,14,1,9,5,13,3,11,7,15};
    float2 y[16];
    #pragma unroll
    for (int j = 0; j < 16; ++j) y[BR[j]] = o[j];
    const float C1 = 0.9238795325112867f, S1 = 0.3826834323650898f, R2 = 0.7071067811865476f;
    const float2 W[8] = {{1.f,0.f},{C1,S1},{R2,R2},{S1,C1},{0.f,1.f},{-S1,C1},{-R2,R2},{-C1,S1}};
    #pragma unroll
    for (int st = 0; st < 4; ++st) {
        int half = 1 << st;
        #pragma unroll
        for (int j = 0; j < 8; ++j) {
            int pos = j & (half - 1);
            int b2 = ((j >> st) << (st + 1)) + pos;
            float2 w = W[pos << (3 - st)];
            float2 a = y[b2];
            float2 t = cmul(y[b2 + half], w);
            y[b2]        = cadd(a, t);
            y[b2 + half] = csub(a, t);
        }
    }
    const float sc = 1.0f / 16.0f;
    float2* dst = d_work + (size_t)bh * HD * NHW + n;
    #pragma unroll
    for (int k = 0; k < 16; ++k)
        dst[(size_t)k * NHW] = make_float2(y[k].x*sc, y[k].y*sc);
}

// ---- 16384-point IFFT per row + abs -> d_outf (padded, table twiddles) ----
#define IX(i) ((i) + ((i) >> 5))
__global__ void ifft_row_kernel() {
    extern __shared__ unsigned char s_raw[];
    float2* dat = (float2*)s_raw;        // padded: 16896
    float2* tw  = dat + 16896;           // 8192
    __shared__ float2 hi[128], lo[64];
    int tid = threadIdx.x;               // 1024
    int row = blockIdx.x;                // b*128 + c
    if (tid < 128) {
        float sv, cv; sincospif((float)tid * (1.0f/128.0f), &sv, &cv);
        hi[tid] = make_float2(cv, sv);
    } else if (tid < 192) {
        int j = tid - 128;
        float sv, cv; sincospif((float)j * (1.0f/8192.0f), &sv, &cv);
        lo[j] = make_float2(cv, sv);
    }
    __syncthreads();
    for (int j = tid; j < 8192; j += 1024)
        tw[j] = cmul(hi[j >> 6], lo[j & 63]);
    const float2* src = d_work + (size_t)row * NHW;
    for (int j = tid; j < 16384; j += 1024) {
        int p = __brev(j) >> 18;
        dat[IX(p)] = src[j];
    }
    __syncthreads();
    #pragma unroll
    for (int st = 0; st < 14; st += 2) {
        int h = 1 << st;
        for (int idx = tid; idx < 4096; idx += 1024) {
            int pos = idx & (h - 1);
            int q = ((idx >> st) << (st + 2)) + pos;
            float2 a = dat[IX(q)], b = dat[IX(q+h)], c = dat[IX(q+2*h)], d = dat[IX(q+3*h)];
            float2 w1 = tw[pos << (13 - st)];
            float2 t  = cmul(b, w1);
            float2 u0 = cadd(a, t), u1 = csub(a, t);
            float2 t2 = cmul(d, w1);
            float2 u2 = cadd(c, t2), u3 = csub(c, t2);
            float2 w2 = tw[pos << (12 - st)];
            float2 w3 = tw[(pos + h) << (12 - st)];
            float2 v  = cmul(u2, w2);
            dat[IX(q)]     = cadd(u0, v);
            dat[IX(q+2*h)] = csub(u0, v);
            float2 v2 = cmul(u3, w3);
            dat[IX(q+h)]   = cadd(u1, v2);
            dat[IX(q+3*h)] = csub(u1, v2);
        }
        __syncthreads();
    }
    float* dst = d_outf + (size_t)row * NHW;
    const float sc = 1.0f / 16384.0f;
    for (int j = tid; j < 16384; j += 1024) {
        float2 v = dat[IX(j)];
        dst[j] = sqrtf(v.x*v.x + v.y*v.y) * sc;
    }
}

// ---------------- SE gate; d_work = g * xf (xf tile cached once) ----------------
__global__ void gate_kernel(const float* __restrict__ w1, const float* __restrict__ b1,
                            const float* __restrict__ bn_g, const float* __restrict__ bn_b,
                            const float* __restrict__ bn_m, const float* __restrict__ bn_v,
                            const float* __restrict__ w2, const float* __restrict__ b2) {
    extern __shared__ unsigned char s_raw[];
    float2* xc = (float2*)s_raw;              // [128][65]
    float* w1s = (float*)(xc + 128*65);       // [8][128]
    float* w2s = w1s + 1024;                  // [128][8]
    float* hid = w2s + 1024;                  // [8][65]
    int tid = threadIdx.x;
    int pp0 = blockIdx.x * 64;
    int b = pp0 >> 14, p0 = pp0 & (NHW-1);
    size_t sbase = (size_t)(b*128) * NHW + p0;
    for (int i = tid; i < 1024; i += 256) { w1s[i] = w1[i]; w2s[i] = w2[i]; }
    for (int i = tid; i < 8192; i += 256) {
        int cc = i >> 6, px = i & 63;
        xc[cc*65 + px] = d_xf[sbase + (size_t)cc * NHW + px];
    }
    __syncthreads();
    for (int t = tid; t < 512; t += 256) {
        int hc = t >> 6, px = t & 63;
        float h = b1[hc];
        #pragma unroll 8
        for (int cc = 0; cc < 128; ++cc) h += w1s[hc*128 + cc] * xc[cc*65 + px].x;
        h = (h - bn_m[hc]) * rsqrtf(bn_v[hc] + 1e-5f) * bn_g[hc] + bn_b[hc];
        hid[hc*65 + px] = fmaxf(h, 0.0f);
    }
    __syncthreads();
    for (int t = tid; t < 8192; t += 256) {
        int oc = t >> 6, px = t & 63;
        float sv = b2[oc];
        #pragma unroll
        for (int hc = 0; hc < 8; ++hc) sv += w2s[oc*8 + hc] * hid[hc*65 + px];
        float gg = 1.0f / (1.0f + expf(-sv));
        float2 xv = xc[oc*65 + px];
        d_work[sbase + (size_t)oc * NHW + px] = make_float2(gg*xv.x, gg*xv.y);
    }
}

// ---------------- 1x1 conv (128->128, bias), FFMA2 packed over oc pairs ----------------
__global__ void conv1x1_kernel(const float* __restrict__ in, const float* __restrict__ w,
                               const float* __restrict__ bias, float* __restrict__ out) {
    extern __shared__ unsigned char s_raw[];
    float* wt = (float*)s_raw;        // [128 ic][134]  (oc fast, transposed)
    float* xs = wt + 128*134;         // [128 ic][68]
    int tid = threadIdx.x;
    int pp0 = blockIdx.x * 64;
    int b = pp0 >> 14, p0 = pp0 & (NHW-1);
    for (int i = tid; i < 16384; i += 256) {
        int oc = i >> 7, ic = i & 127;
        wt[ic*134 + oc] = w[i];
    }
    for (int i = tid; i < 8192; i += 256) {
        int cc = i >> 6, px = i & 63;
        xs[cc*68 + px] = in[(size_t)(b*128 + cc) * NHW + p0 + px];
    }
    __syncthreads();
    int ocg = tid >> 4, pxg = tid & 15;
    int ocb = ocg * 8;
    unsigned long long acc2[4][4];
    #pragma unroll
    for (int p = 0; p < 4; ++p) {
        unsigned long long bp = pk2(bias[ocb + 2*p], bias[ocb + 2*p + 1]);
        #pragma unroll
        for (int v = 0; v < 4; ++v) acc2[p][v] = bp;
    }
    #pragma unroll 4
    for (int i = 0; i < 128; ++i) {
        float4 xv = *(const float4*)&xs[i*68 + pxg*4];
        unsigned long long xd0 = pk2(xv.x, xv.x);
        unsigned long long xd1 = pk2(xv.y, xv.y);
        unsigned long long xd2 = pk2(xv.z, xv.z);
        unsigned long long xd3 = pk2(xv.w, xv.w);
        const float* wrow = &wt[i*134 + ocb];
        #pragma unroll
        for (int p = 0; p < 4; ++p) {
            unsigned long long w2 = *(const unsigned long long*)&wrow[2*p];
            ffma2(acc2[p][0], w2, xd0);
            ffma2(acc2[p][1], w2, xd1);
            ffma2(acc2[p][2], w2, xd2);
            ffma2(acc2[p][3], w2, xd3);
        }
    }
    #pragma unroll
    for (int p = 0; p < 4; ++p) {
        float2 a0 = upk2(acc2[p][0]), a1 = upk2(acc2[p][1]);
        float2 a2 = upk2(acc2[p][2]), a3 = upk2(acc2[p][3]);
        int oc = ocb + 2*p;
        *(float4*)&out[(size_t)(b*128 + oc    ) * NHW + p0 + pxg*4] = make_float4(a0.x, a1.x, a2.x, a3.x);
        *(float4*)&out[(size_t)(b*128 + oc + 1) * NHW + p0 + pxg*4] = make_float4(a0.y, a1.y, a2.y, a3.y);
    }
}

// ------- grouped conv3 + conv5 (concat): 32x32 tile, FFMA2, packed weights -------
__global__ void gconv_kernel(const float* __restrict__ in, const float* __restrict__ w3,
                             const float* __restrict__ w5, float* __restrict__ out) {
    __shared__ float t0[36*40], t1[36*40];             // halo tiles, pitch 40 (16B aligned rows)
    __shared__ unsigned long long wp3[2][9], wp5[2][25]; // packed (w,w)
    int tid = threadIdx.x;
    int tile = blockIdx.x, g = blockIdx.y, b = blockIdx.z;
    int ty0 = (tile >> 2) * 32, tx0 = (tile & 3) * 32;
    const float* in0 = in + (size_t)(b*128 + 2*g) * NHW;
    const float* in1 = in0 + NHW;
    for (int i = tid; i < 1296; i += 256) {
        int ly = i / 36, lx = i % 36;
        int gy = ty0 - 2 + ly, gx = tx0 - 2 + lx;
        bool ok = ((unsigned)gy < 128u) && ((unsigned)gx < 128u);
        t0[ly*40 + lx] = ok ? in0[gy*128 + gx] : 0.f;
        t1[ly*40 + lx] = ok ? in1[gy*128 + gx] : 0.f;
    }
    if (tid < 18) {
        int ch = tid / 9, k = tid % 9;
        float w = w3[(g*2 + ch)*9 + k];
        wp3[ch][k] = pk2(w, w);
    } else if (tid >= 32 && tid < 82) {
        int t2 = tid - 32;
        int ch = t2 / 25, k = t2 % 25;
        float w = w5[(g*2 + ch)*25 + k];
        wp5[ch][k] = pk2(w, w);
    }
    __syncthreads();
    int ty = tid >> 3;             // 0..31
    int tx = (tid & 7) * 4;        // 0,4,...,28
    unsigned long long a3q0 = 0ULL, a3q1 = 0ULL, a5q0 = 0ULL, a5q1 = 0ULL;
    #pragma unroll
    for (int ch = 0; ch < 2; ++ch) {
        const float* t = ch ? t1 : t0;
        #pragma unroll
        for (int ky = 0; ky < 5; ++ky) {
            const float* row = &t[(ty + ky)*40 + tx];
            float4 rA = *(const float4*)row;
            float4 rB = *(const float4*)(row + 4);
            float r0 = rA.x, r1 = rA.y, r2 = rA.z, r3 = rA.w;
            float r4 = rB.x, r5 = rB.y, r6 = rB.z, r7 = rB.w;
            unsigned long long p0 = pk2(r0, r1), p1 = pk2(r1, r2), p2 = pk2(r2, r3);
            unsigned long long p3 = pk2(r3, r4), p4 = pk2(r4, r5), p5 = pk2(r5, r6);
            unsigned long long p6 = pk2(r6, r7);
            unsigned long long pr[7] = { p0, p1, p2, p3, p4, p5, p6 };
            #pragma unroll
            for (int kx = 0; kx < 5; ++kx) {
                unsigned long long w = wp5[ch][ky*5 + kx];
                ffma2(a5q0, w, pr[kx]);
                ffma2(a5q1, w, pr[kx + 2]);
            }
            if (ky >= 1 && ky <= 3) {
                #pragma unroll
                for (int kx = 0; kx < 3; ++kx) {
                    unsigned long long w = wp3[ch][(ky - 1)*3 + kx];
                    ffma2(a3q0, w, pr[1 + kx]);
                    ffma2(a3q1, w, pr[3 + kx]);
                }
            }
        }
    }
    int py = ty0 + ty, px = tx0 + tx;
    float2 a30 = upk2(a3q0), a31 = upk2(a3q1);
    float2 a50 = upk2(a5q0), a51 = upk2(a5q1);
    *(float4*)&out[(size_t)(b*128 + g)      * NHW + py*128 + px] = make_float4(a30.x, a30.y, a31.x, a31.y);
    *(float4*)&out[(size_t)(b*128 + 64 + g) * NHW + py*128 + px] = make_float4(a50.x, a50.y, a51.x, a51.y);
}

// ---------------- gram S partials (float4 loads, pitch 516) ----------------
__global__ void gram_s_part_kernel() {
    extern __shared__ unsigned char s_raw[];
    float* sq = (float*)s_raw;           // [16][516]
    float* sk = sq + 16*516;             // [16][516]
    int bh = blockIdx.x;
    int ns = blockIdx.y;
    int tid = threadIdx.x;
    int c = tid >> 4, d = tid & 15;
    const float* qb = d_q + (size_t)bh * HD * NHW + ns * (NHW / NS);
    const float* kb = d_k + (size_t)bh * HD * NHW + ns * (NHW / NS);
    float acc = 0.f, nq = 0.f, nk = 0.f;
    for (int ch = 0; ch < NHW / NS; ch += 512) {
        for (int i = tid; i < 8192; i += 256) {
            int hh = i >> 9, j = i & 511;
            sq[hh*516 + j] = qb[(size_t)hh*NHW + ch + j];
            sk[hh*516 + j] = kb[(size_t)hh*NHW + ch + j];
        }
        __syncthreads();
        #pragma unroll 4
        for (int j = 0; j < 512; j += 4) {
            float4 A = *(const float4*)&sq[c*516 + j];
            float4 B = *(const float4*)&sk[d*516 + j];
            acc += A.x*B.x + A.y*B.y + A.z*B.z + A.w*B.w;
            if (c == d) {
                nq += A.x*A.x + A.y*A.y + A.z*A.z + A.w*A.w;
                nk += B.x*B.x + B.y*B.y + B.z*B.z + B.w*B.w;
            }
        }
        __syncthreads();
    }
    int part = bh * NS + ns;
    d_gsp[part*256 + tid] = acc;
    if (c == d) { d_gsq[part*16 + c] = nq; d_gsk[part*16 + c] = nk; }
}

// ---------------- gram S finalize ----------------
__global__ void attns_finalize_kernel(const float* __restrict__ temp_s) {
    __shared__ float snq[16], snk[16];
    __shared__ float sA[16][17];
    int bh = blockIdx.x;
    int tid = threadIdx.x;
    int c = tid >> 4, d = tid & 15;
    float acc = 0.f;
    #pragma unroll
    for (int ns = 0; ns < NS; ++ns) acc += d_gsp[(bh*NS + ns)*256 + tid];
    if (tid < 16) {
        float nq = 0.f, nk = 0.f;
        #pragma unroll
        for (int ns = 0; ns < NS; ++ns) {
            nq += d_gsq[(bh*NS + ns)*16 + tid];
            nk += d_gsk[(bh*NS + ns)*16 + tid];
        }
        snq[tid] = fmaxf(sqrtf(nq), 1e-12f);
        snk[tid] = fmaxf(sqrtf(nk), 1e-12f);
    }
    __syncthreads();
    sA[c][d] = acc * temp_s[bh & 7] / (snq[c] * snk[d]);
    __syncthreads();
    if (tid < 16) {
        int row = tid;
        float m = -1e30f;
        #pragma unroll
        for (int dd = 0; dd < 16; ++dd) m = fmaxf(m, sA[row][dd]);
        float e[16], s = 0.f;
        #pragma unroll
        for (int dd = 0; dd < 16; ++dd) { e[dd] = expf(sA[row][dd] - m); s += e[dd]; }
        float is = 1.f / s;
        #pragma unroll
        for (int dd = 0; dd < 16; ++dd) d_attns[bh*256 + row*16 + dd] = e[dd] * is;
    }
}

// ---------------- out_s = attn_s @ v -> d_bufT (FFMA2 over cc pairs) ----------------
__global__ void __launch_bounds__(256, 4) apply_attn_s_kernel() {
    __shared__ ulonglong2 At[64];   // [dd][pq]: pq covers cc pairs (4pq..4pq+3)
    int bh = blockIdx.x, nb = blockIdx.y;
    int tid = threadIdx.x;
    if (tid < 64) {
        int dd = tid >> 2, pq = tid & 3;
        const float* Ab = d_attns + bh*256;
        At[tid] = make_ulonglong2(
            pk2(Ab[(4*pq    )*16 + dd], Ab[(4*pq + 1)*16 + dd]),
            pk2(Ab[(4*pq + 2)*16 + dd], Ab[(4*pq + 3)*16 + dd]));
    }
    __syncthreads();
    int n = nb*256 + tid;
    const float* vb = d_v + (size_t)bh * HD * NHW + n;
    unsigned long long o2[8];
    #pragma unroll
    for (int p = 0; p < 8; ++p) o2[p] = 0ULL;
    #pragma unroll
    for (int dd = 0; dd < 16; ++dd) {
        float vv = vb[(size_t)dd * NHW];
        unsigned long long vd = pk2(vv, vv);
        #pragma unroll
        for (int pq = 0; pq < 4; ++pq) {
            ulonglong2 ap = At[dd*4 + pq];
            ffma2(o2[pq*2    ], ap.x, vd);
            ffma2(o2[pq*2 + 1], ap.y, vd);
        }
    }
    float* dst = d_bufT + (size_t)bh * HD * NHW + n;
    #pragma unroll
    for (int p = 0; p < 8; ++p) {
        float2 o = upk2(o2[p]);
        dst[(size_t)(2*p    ) * NHW] = o.x;
        dst[(size_t)(2*p + 1) * NHW] = o.y;
    }
}

// ---------------- final fused projection (fsa + ssa), FFMA2 ----------------
__global__ void final_conv_kernel(const float* __restrict__ pfw, const float* __restrict__ psw,
                                  float* __restrict__ out) {
    extern __shared__ unsigned char s_raw[];
    float* wt = (float*)s_raw;        // [128 ic][134]
    float* xs = wt + 128*134;         // [128 ic][68]
    int tid = threadIdx.x;
    int pp0 = blockIdx.x * 64;
    int b = pp0 >> 14, p0 = pp0 & (NHW-1);
    int ocg = tid >> 4, pxg = tid & 15;
    int ocb = ocg * 8;
    unsigned long long acc2[4][4];
    #pragma unroll
    for (int p = 0; p < 4; ++p)
        #pragma unroll
        for (int v = 0; v < 4; ++v) acc2[p][v] = 0ULL;
    const float* ins[4] = { d_outf, d_outfl, d_bufT, d_outsl };
    for (int pass = 0; pass < 4; ++pass) {
        const float* wsrc = (pass < 2) ? pfw : psw;
        int off = (pass & 1) * 128;
        for (int i = tid; i < 16384; i += 256) {
            int oc = i >> 7, ic = i & 127;
            wt[ic*134 + oc] = wsrc[oc*256 + off + ic];
        }
        const float* in = ins[pass];
        for (int i = tid; i < 8192; i += 256) {
            int cc = i >> 6, px = i & 63;
            xs[cc*68 + px] = in[(size_t)(b*128 + cc) * NHW + p0 + px];
        }
        __syncthreads();
        #pragma unroll 4
        for (int i = 0; i < 128; ++i) {
            float4 xv = *(const float4*)&xs[i*68 + pxg*4];
            unsigned long long xd0 = pk2(xv.x, xv.x);
            unsigned long long xd1 = pk2(xv.y, xv.y);
            unsigned long long xd2 = pk2(xv.z, xv.z);
            unsigned long long xd3 = pk2(xv.w, xv.w);
            const float* wrow = &wt[i*134 + ocb];
            #pragma unroll
            for (int p = 0; p < 4; ++p) {
                unsigned long long w2 = *(const unsigned long long*)&wrow[2*p];
                ffma2(acc2[p][0], w2, xd0);
                ffma2(acc2[p][1], w2, xd1);
                ffma2(acc2[p][2], w2, xd2);
                ffma2(acc2[p][3], w2, xd3);
            }
        }
        __syncthreads();
    }
    #pragma unroll
    for (int p = 0; p < 4; ++p) {
        float2 a0 = upk2(acc2[p][0]), a1 = upk2(acc2[p][1]);
        float2 a2 = upk2(acc2[p][2]), a3 = upk2(acc2[p][3]);
        int oc = ocb + 2*p;
        *(float4*)&out[(size_t)(b*128 + oc    ) * NHW + p0 + pxg*4] = make_float4(a0.x, a1.x, a2.x, a3.x);
        *(float4*)&out[(size_t)(b*128 + oc + 1) * NHW + p0 + pxg*4] = make_float4(a0.y, a1.y, a2.y, a3.y);
    }
}

// ---------------- host launcher ----------------
#define SM_FFT2  ((128*FPITCH + 64) * (int)sizeof(float2))      // 132,608
#define SM_ROW   ((16896 + 8192) * (int)sizeof(float2))         // 200,704
#define SM_GRAMF (16*514 * (int)sizeof(float2))                 //  65,792
#define SM_GRAMS (2*16*516 * (int)sizeof(float))                //  66,048
#define SM_CONV  ((128*134 + 128*68) * (int)sizeof(float))      // 103,424
#define SM_GATE  ((128*65) * (int)sizeof(float2) + (1024 + 1024 + 8*65) * (int)sizeof(float))

extern "C" void kernel_launch(void* const* d_in, const int* in_sizes, int n_in,
                              void* d_out, int out_size) {
    (void)in_sizes; (void)n_in; (void)out_size;
    const float* x       = (const float*)d_in[0];
    const float* temp_f  = (const float*)d_in[1];
    const float* w1      = (const float*)d_in[2];
    const float* b1      = (const float*)d_in[3];
    const float* bn_g    = (const float*)d_in[4];
    const float* bn_b    = (const float*)d_in[5];
    const float* bn_m    = (const float*)d_in[6];
    const float* bn_v    = (const float*)d_in[7];
    const float* w2      = (const float*)d_in[8];
    const float* b2      = (const float*)d_in[9];
    const float* projf_w = (const float*)d_in[10];
    const float* temp_s  = (const float*)d_in[11];
    const float* q1_w = (const float*)d_in[12];
    const float* q1_b = (const float*)d_in[13];
    const float* k1_w = (const float*)d_in[14];
    const float* k1_b = (const float*)d_in[15];
    const float* v1_w = (const float*)d_in[16];
    const float* v1_b = (const float*)d_in[17];
    const float* q3_w = (const float*)d_in[18];
    const float* q5_w = (const float*)d_in[19];
    const float* k3_w = (const float*)d_in[20];
    const float* k5_w = (const float*)d_in[21];
    const float* v3_w = (const float*)d_in[22];
    const float* v5_w = (const float*)d_in[23];
    const float* c3_w = (const float*)d_in[24];
    const float* c5_w = (const float*)d_in[25];
    const float* projs_w = (const float*)d_in[26];
    float* out = (float*)d_out;

    cudaFuncSetAttribute(fft2_fwd_kernel,    cudaFuncAttributeMaxDynamicSharedMemorySize, SM_FFT2);
    cudaFuncSetAttribute(ifft2_abs_kernel,   cudaFuncAttributeMaxDynamicSharedMemorySize, SM_FFT2);
    cudaFuncSetAttribute(ifft_row_kernel,    cudaFuncAttributeMaxDynamicSharedMemorySize, SM_ROW);
    cudaFuncSetAttribute(gram_f_part_kernel, cudaFuncAttributeMaxDynamicSharedMemorySize, SM_GRAMF);
    cudaFuncSetAttribute(gram_s_part_kernel, cudaFuncAttributeMaxDynamicSharedMemorySize, SM_GRAMS);
    cudaFuncSetAttribute(conv1x1_kernel,     cudaFuncAttributeMaxDynamicSharedMemorySize, SM_CONV);
    cudaFuncSetAttribute(final_conv_kernel,  cudaFuncAttributeMaxDynamicSharedMemorySize, SM_CONV);
    cudaFuncSetAttribute(gate_kernel,        cudaFuncAttributeMaxDynamicSharedMemorySize, SM_GATE);

    float *pT, *pQ, *pK, *pV, *pSL, *ptq, *ptk;
    cudaGetSymbolAddress((void**)&pT,  d_bufT);
    cudaGetSymbolAddress((void**)&pQ,  d_q);
    cudaGetSymbolAddress((void**)&pK,  d_k);
    cudaGetSymbolAddress((void**)&pV,  d_v);
    cudaGetSymbolAddress((void**)&pSL, d_outsl);
    cudaGetSymbolAddress((void**)&ptq, d_tq);
    cudaGetSymbolAddress((void**)&ptk, d_tk);
    float* tq = ptq;     // dedicated scratch (no overlay with freq branch)
    float* tk = ptk;
    float* tv = pT;      // d_bufT is spatial-branch-only

    // One-time creation of the fork stream + events (resource init only; the
    // launched work is identical on every call).
    static cudaStream_t s_sp = nullptr;
    static cudaEvent_t ev_fork = nullptr, ev_join = nullptr;
    if (s_sp == nullptr) {
        cudaStreamCreateWithFlags(&s_sp, cudaStreamNonBlocking);
        cudaEventCreateWithFlags(&ev_fork, cudaEventDisableTiming);
        cudaEventCreateWithFlags(&ev_join, cudaEventDisableTiming);
    }

    // ---- fork: spatial branch runs on s_sp concurrently with freq branch ----
    cudaEventRecord(ev_fork, 0);
    cudaStreamWaitEvent(s_sp, ev_fork, 0);

    // ---- spatial branch (stream s_sp) ----
    conv1x1_kernel<<<2048, 256, SM_CONV, s_sp>>>(x, q1_w, q1_b, tq);
    gconv_kernel<<<dim3(16, 64, 8), 256, 0, s_sp>>>(tq, q3_w, q5_w, pQ);
    conv1x1_kernel<<<2048, 256, SM_CONV, s_sp>>>(x, k1_w, k1_b, tk);
    gconv_kernel<<<dim3(16, 64, 8), 256, 0, s_sp>>>(tk, k3_w, k5_w, pK);
    conv1x1_kernel<<<2048, 256, SM_CONV, s_sp>>>(x, v1_w, v1_b, tv);
    gconv_kernel<<<dim3(16, 64, 8), 256, 0, s_sp>>>(tv, v3_w, v5_w, pV);
    gconv_kernel<<<dim3(16, 64, 8), 256, 0, s_sp>>>(x, c3_w, c5_w, pSL);
    gram_s_part_kernel<<<dim3(64, NS), 256, SM_GRAMS, s_sp>>>();
    attns_finalize_kernel<<<64, 256, 0, s_sp>>>(temp_s);
    apply_attn_s_kernel<<<dim3(64, 64), 256, 0, s_sp>>>();   // writes d_bufT (out_s)

    // ---- frequency branch (capture/legacy stream) ----
    fft2_fwd_kernel<<<1024, 512, SM_FFT2>>>(x);
    gram_f_part_kernel<<<dim3(64, NS), 256, SM_GRAMF>>>();
    attnf_finalize_kernel<<<64, 256>>>(temp_f);
    apply_attn_f_kernel<<<dim3(64, 64), 256>>>();   // fused with ifft16
    ifft_row_kernel<<<1024, 1024, SM_ROW>>>();
    gate_kernel<<<2048, 256, SM_GATE>>>(w1, b1, bn_g, bn_b, bn_m, bn_v, w2, b2);
    ifft2_abs_kernel<<<1024, 512, SM_FFT2>>>();

    // ---- join: final projection needs both branches ----
    cudaEventRecord(ev_join, s_sp);
    cudaStreamWaitEvent(0, ev_join, 0);
    final_conv_kernel<<<2048, 256, SM_CONV>>>(projf_w, projs_w, out);
}

// round 14
// speedup vs baseline: 1.1591x; 1.0003x over previous
#include <cuda_runtime.h>
#include <cstdint>

// ---------------- problem constants ----------------
#define NB     8
#define NC     128
#define NHW    16384            // 128*128
#define NHEADS 8
#define HD     16               // head dim (channels per head)
#define NELEM  16777216         // NB*NC*NHW
#define NS     16               // gram n-split

#define FPITCH 129              // 128x128 fft tile pitch (float2)

// ---------------- scratch (device globals; no allocs allowed) ----------------
__device__ float2 d_xf[NELEM];      // fft2(x)
__device__ float2 d_work[NELEM];    // out_cplx(post ifft16) / g*xf  (freq branch ONLY)
__device__ float  d_outf[NELEM];    // |ifft2(out_cplx)|
__device__ float  d_outfl[NELEM];   // |ifft2(g*xf)|
__device__ float  d_q[NELEM];
__device__ float  d_k[NELEM];
__device__ float  d_v[NELEM];
__device__ float  d_outsl[NELEM];
__device__ float  d_bufT[NELEM];    // v-temp, then out_s (spatial branch)
__device__ float  d_tq[NELEM];      // q-temp (spatial branch)
__device__ float  d_tk[NELEM];      // k-temp (spatial branch)
__device__ float2 d_attnf[NB*NHEADS*HD*HD];
__device__ float  d_attns[NB*NHEADS*HD*HD];
// gram partials
__device__ float2 d_gfp[NB*NHEADS*NS*256];
__device__ float  d_gfn[NB*NHEADS*NS*16];
__device__ float  d_gsp[NB*NHEADS*NS*256];
__device__ float  d_gsq[NB*NHEADS*NS*16];
__device__ float  d_gsk[NB*NHEADS*NS*16];

// ---------------- helpers ----------------
__device__ __forceinline__ float2 cmul(float2 a, float2 b) {
    return make_float2(a.x*b.x - a.y*b.y, a.x*b.y + a.y*b.x);
}
__device__ __forceinline__ float2 cadd(float2 a, float2 b) { return make_float2(a.x+b.x, a.y+b.y); }
__device__ __forceinline__ float2 csub(float2 a, float2 b) { return make_float2(a.x-b.x, a.y-b.y); }
__device__ __forceinline__ int brev7(int v) { return __brev(v) >> 25; }

// ---- packed fp32x2 (Blackwell FFMA2 path) ----
__device__ __forceinline__ unsigned long long pk2(float a, float b) {
    unsigned long long r;
    asm("mov.b64 %0, {%1, %2};" : "=l"(r) : "f"(a), "f"(b));
    return r;
}
__device__ __forceinline__ void ffma2(unsigned long long& c, unsigned long long a, unsigned long long b) {
    asm("fma.rn.f32x2 %0, %1, %2, %0;" : "+l"(c) : "l"(a), "l"(b));
}
__device__ __forceinline__ float2 upk2(unsigned long long v) {
    float2 r;
    asm("mov.b64 {%0, %1}, %2;" : "=f"(r.x), "=f"(r.y) : "l"(v));
    return r;
}

// ============ 2D 128x128 FFT (radix-2^2), input loaded bit-reversed ============
// tw[j] = exp(dir*i*pi*j/64), j in [0,64). NT = threads.
// Column stages are ROW-FAST so LDS/STS are conflict-free.
template <int NT>
__device__ void fft2_128_r4(float2* s, const float2* tw, int tid) {
    #pragma unroll
    for (int st = 0; st < 6; st += 2) {
        int h = 1 << st;
        for (int idx = tid; idx < 4096; idx += NT) {
            int r = idx & 127, j = idx >> 7;      // j in [0,32)
            int pos = j & (h - 1);
            int q = ((j >> st) << (st + 2)) + pos;
            float2* row = s + r * FPITCH;
            float2 a = row[q], b = row[q+h], c = row[q+2*h], d = row[q+3*h];
            float2 w1 = tw[pos << (6 - st)];
            float2 t  = cmul(b, w1);
            float2 u0 = cadd(a, t), u1 = csub(a, t);
            float2 t2 = cmul(d, w1);
            float2 u2 = cadd(c, t2), u3 = csub(c, t2);
            float2 w2 = tw[pos << (5 - st)];
            float2 w3 = tw[(pos + h) << (5 - st)];
            float2 v  = cmul(u2, w2);
            row[q]       = cadd(u0, v);
            row[q+2*h]   = csub(u0, v);
            float2 v2 = cmul(u3, w3);
            row[q+h]     = cadd(u1, v2);
            row[q+3*h]   = csub(u1, v2);
        }
        __syncthreads();
    }
    for (int idx = tid; idx < 8192; idx += NT) {
        int r = idx & 127, pos = idx >> 7;        // pos in [0,64)
        float2 w = tw[pos];
        float2* p0 = &s[r*FPITCH + pos];
        float2* p1 = &s[r*FPITCH + pos + 64];
        float2 a = *p0, t = cmul(*p1, w);
        *p0 = cadd(a, t);
        *p1 = csub(a, t);
    }
    __syncthreads();
    #pragma unroll
    for (int st = 0; st < 6; st += 2) {
        int h = 1 << st;
        for (int idx = tid; idx < 4096; idx += NT) {
            int c0 = idx & 127, j = idx >> 7;
            int pos = j & (h - 1);
            int q = ((j >> st) << (st + 2)) + pos;
            float2 a = s[(q      )*FPITCH + c0];
            float2 b = s[(q +   h)*FPITCH + c0];
            float2 c = s[(q + 2*h)*FPITCH + c0];
            float2 d = s[(q + 3*h)*FPITCH + c0];
            float2 w1 = tw[pos << (6 - st)];
            float2 t  = cmul(b, w1);
            float2 u0 = cadd(a, t), u1 = csub(a, t);
            float2 t2 = cmul(d, w1);
            float2 u2 = cadd(c, t2), u3 = csub(c, t2);
            float2 w2 = tw[pos << (5 - st)];
            float2 w3 = tw[(pos + h) << (5 - st)];
            float2 v  = cmul(u2, w2);
            s[(q      )*FPITCH + c0] = cadd(u0, v);
            s[(q + 2*h)*FPITCH + c0] = csub(u0, v);
            float2 v2 = cmul(u3, w3);
            s[(q +   h)*FPITCH + c0] = cadd(u1, v2);
            s[(q + 3*h)*FPITCH + c0] = csub(u1, v2);
        }
        __syncthreads();
    }
    for (int idx = tid; idx < 8192; idx += NT) {
        int c0 = idx & 127, pos = idx >> 7;
        float2 w = tw[pos];
        float2* p0 = &s[pos*FPITCH + c0];
        float2* p1 = &s[(pos + 64)*FPITCH + c0];
        float2 a = *p0, t = cmul(*p1, w);
        *p0 = cadd(a, t);
        *p1 = csub(a, t);
    }
    __syncthreads();
}

// ---------------- forward FFT2 of x -> d_xf ----------------
__global__ void fft2_fwd_kernel(const float* __restrict__ x) {
    extern __shared__ unsigned char s_raw[];
    float2* s = (float2*)s_raw;
    float2* tw = s + 128*FPITCH;
    int tid = threadIdx.x;  // 512
    int slice = blockIdx.x; // b*128 + c
    if (tid < 64) {
        float sv, cv; sincospif(-(float)tid * (1.0f/64.0f), &sv, &cv);
        tw[tid] = make_float2(cv, sv);
    }
    const float* xin = x + (size_t)slice * NHW;
    for (int idx = tid; idx < 16384; idx += 512) {
        int r = idx >> 7, c = idx & 127;
        s[brev7(r)*FPITCH + brev7(c)] = make_float2(xin[idx], 0.0f);
    }
    __syncthreads();
    fft2_128_r4<512>(s, tw, tid);
    float2* dst = d_xf + (size_t)slice * NHW;
    for (int idx = tid; idx < 16384; idx += 512) {
        int r = idx >> 7, c = idx & 127;
        dst[idx] = s[r*FPITCH + c];
    }
}

// ---------------- inverse FFT2 + abs of d_work -> d_outfl ----------------
__global__ void ifft2_abs_kernel() {
    extern __shared__ unsigned char s_raw[];
    float2* s = (float2*)s_raw;
    float2* tw = s + 128*FPITCH;
    int tid = threadIdx.x;  // 512
    int slice = blockIdx.x;
    if (tid < 64) {
        float sv, cv; sincospif((float)tid * (1.0f/64.0f), &sv, &cv);
        tw[tid] = make_float2(cv, sv);
    }
    const float2* xin = d_work + (size_t)slice * NHW;
    for (int idx = tid; idx < 16384; idx += 512) {
        int r = idx >> 7, c = idx & 127;
        s[brev7(r)*FPITCH + brev7(c)] = xin[idx];
    }
    __syncthreads();
    fft2_128_r4<512>(s, tw, tid);
    float* dst = d_outfl + (size_t)slice * NHW;
    const float sc = 1.0f / 16384.0f;
    for (int idx = tid; idx < 16384; idx += 512) {
        int r = idx >> 7, c = idx & 127;
        float2 v = s[r*FPITCH + c];
        dst[idx] = sqrtf(v.x*v.x + v.y*v.y) * sc;
    }
}

// ---------------- gram F partials (float4 loads, pitch 514) ----------------
__global__ void gram_f_part_kernel() {
    extern __shared__ unsigned char s_raw[];
    float2* sq = (float2*)s_raw;      // [16][514]
    int bh = blockIdx.x;              // b*8 + head
    int ns = blockIdx.y;              // n-chunk
    int tid = threadIdx.x;
    int c = tid >> 4, d = tid & 15;
    float2 acc = make_float2(0.f, 0.f);
    float nrm = 0.f;
    const float2* base = d_xf + (size_t)bh * HD * NHW + ns * (NHW / NS);
    for (int ch = 0; ch < NHW / NS; ch += 512) {
        for (int i = tid; i < 8192; i += 256) {
            int hh = i >> 9, j = i & 511;
            sq[hh*514 + j] = base[(size_t)hh*NHW + ch + j];
        }
        __syncthreads();
        #pragma unroll 4
        for (int j = 0; j < 512; j += 2) {
            float4 A = *(const float4*)&sq[c*514 + j];
            float4 B = *(const float4*)&sq[d*514 + j];
            acc.x += A.x*B.x - A.y*B.y;
            acc.y += A.x*B.y + A.y*B.x;
            acc.x += A.z*B.z - A.w*B.w;
            acc.y += A.z*B.w + A.w*B.z;
            if (c == d) nrm += A.x*A.x + A.y*A.y + A.z*A.z + A.w*A.w;
        }
        __syncthreads();
    }
    int part = bh * NS + ns;
    d_gfp[part*256 + tid] = acc;
    if (c == d) d_gfn[part*16 + c] = nrm;
}

// ---------------- gram F finalize ----------------
__global__ void attnf_finalize_kernel(const float* __restrict__ temp_f) {
    __shared__ float  snrm[16];
    __shared__ float2 sA[16][17];
    int bh = blockIdx.x;
    int tid = threadIdx.x;
    int c = tid >> 4, d = tid & 15;
    float2 acc = make_float2(0.f, 0.f);
    #pragma unroll
    for (int ns = 0; ns < NS; ++ns) {
        float2 p = d_gfp[(bh*NS + ns)*256 + tid];
        acc.x += p.x; acc.y += p.y;
    }
    if (tid < 16) {
        float nrm = 0.f;
        #pragma unroll
        for (int ns = 0; ns < NS; ++ns) nrm += d_gfn[(bh*NS + ns)*16 + tid];
        snrm[tid] = fmaxf(sqrtf(nrm), 1e-12f);
    }
    __syncthreads();
    float tf = temp_f[bh & 7];
    float inv = tf / (snrm[c] * snrm[d]);
    sA[c][d] = make_float2(acc.x * inv, acc.y * inv);
    __syncthreads();
    if (tid < 16) {
        int row = tid;
        float mr = -1e30f, mi = -1e30f;
        #pragma unroll
        for (int dd = 0; dd < 16; ++dd) {
            mr = fmaxf(mr, sA[row][dd].x);
            mi = fmaxf(mi, sA[row][dd].y);
        }
        float er[16], ei[16], sr = 0.f, si = 0.f;
        #pragma unroll
        for (int dd = 0; dd < 16; ++dd) {
            er[dd] = expf(sA[row][dd].x - mr);
            ei[dd] = expf(sA[row][dd].y - mi);
            sr += er[dd]; si += ei[dd];
        }
        float isr = 1.f/sr, isi = 1.f/si;
        #pragma unroll
        for (int dd = 0; dd < 16; ++dd)
            d_attnf[bh*256 + row*16 + dd] = make_float2(er[dd]*isr, ei[dd]*isi);
    }
}

// ------- out_cplx = attn_f @ qf, fused with IFFT-16 along hd (scalar R5 form) -------
__global__ void __launch_bounds__(256, 4) apply_attn_f_kernel() {
    __shared__ float2 A[256];
    int bh = blockIdx.x, nb = blockIdx.y;
    int tid = threadIdx.x;
    A[tid] = d_attnf[bh*256 + tid];
    __syncthreads();
    int n = nb*256 + tid;
    const float2* src = d_xf + (size_t)bh * HD * NHW + n;
    float2 o[16];
    #pragma unroll
    for (int cc = 0; cc < 16; ++cc) o[cc] = make_float2(0.f, 0.f);
    #pragma unroll
    for (int dd = 0; dd < 16; ++dd) {
        float2 qv = src[(size_t)dd * NHW];
        #pragma unroll
        for (int cc = 0; cc < 16; ++cc) {
            float2 a = A[cc*16 + dd];
            o[cc].x += a.x*qv.x - a.y*qv.y;
            o[cc].y += a.x*qv.y + a.y*qv.x;
        }
    }
    const int BR[16] = {0,8,4,12,2,10,6,14,1,9,5,13,3,11,7,15};
    float2 y[16];
    #pragma unroll
    for (int j = 0; j < 16; ++j) y[BR[j]] = o[j];
    const float C1 = 0.9238795325112867f, S1 = 0.3826834323650898f, R2 = 0.7071067811865476f;
    const float2 W[8] = {{1.f,0.f},{C1,S1},{R2,R2},{S1,C1},{0.f,1.f},{-S1,C1},{-R2,R2},{-C1,S1}};
    #pragma unroll
    for (int st = 0; st < 4; ++st) {
        int half = 1 << st;
        #pragma unroll
        for (int j = 0; j < 8; ++j) {
            int pos = j & (half - 1);
            int b2 = ((j >> st) << (st + 1)) + pos;
            float2 w = W[pos << (3 - st)];
            float2 a = y[b2];
            float2 t = cmul(y[b2 + half], w);
            y[b2]        = cadd(a, t);
            y[b2 + half] = csub(a, t);
        }
    }
    const float sc = 1.0f / 16.0f;
    float2* dst = d_work + (size_t)bh * HD * NHW + n;
    #pragma unroll
    for (int k = 0; k < 16; ++k)
        dst[(size_t)k * NHW] = make_float2(y[k].x*sc, y[k].y*sc);
}

// ---- 16384-point IFFT per row + abs -> d_outf (padded, table twiddles) ----
#define IX(i) ((i) + ((i) >> 5))
__global__ void ifft_row_kernel() {
    extern __shared__ unsigned char s_raw[];
    float2* dat = (float2*)s_raw;        // padded: 16896
    float2* tw  = dat + 16896;           // 8192
    __shared__ float2 hi[128], lo[64];
    int tid = threadIdx.x;               // 1024
    int row = blockIdx.x;                // b*128 + c
    if (tid < 128) {
        float sv, cv; sincospif((float)tid * (1.0f/128.0f), &sv, &cv);
        hi[tid] = make_float2(cv, sv);
    } else if (tid < 192) {
        int j = tid - 128;
        float sv, cv; sincospif((float)j * (1.0f/8192.0f), &sv, &cv);
        lo[j] = make_float2(cv, sv);
    }
    __syncthreads();
    for (int j = tid; j < 8192; j += 1024)
        tw[j] = cmul(hi[j >> 6], lo[j & 63]);
    const float2* src = d_work + (size_t)row * NHW;
    for (int j = tid; j < 16384; j += 1024) {
        int p = __brev(j) >> 18;
        dat[IX(p)] = src[j];
    }
    __syncthreads();
    #pragma unroll
    for (int st = 0; st < 14; st += 2) {
        int h = 1 << st;
        for (int idx = tid; idx < 4096; idx += 1024) {
            int pos = idx & (h - 1);
            int q = ((idx >> st) << (st + 2)) + pos;
            float2 a = dat[IX(q)], b = dat[IX(q+h)], c = dat[IX(q+2*h)], d = dat[IX(q+3*h)];
            float2 w1 = tw[pos << (13 - st)];
            float2 t  = cmul(b, w1);
            float2 u0 = cadd(a, t), u1 = csub(a, t);
            float2 t2 = cmul(d, w1);
            float2 u2 = cadd(c, t2), u3 = csub(c, t2);
            float2 w2 = tw[pos << (12 - st)];
            float2 w3 = tw[(pos + h) << (12 - st)];
            float2 v  = cmul(u2, w2);
            dat[IX(q)]     = cadd(u0, v);
            dat[IX(q+2*h)] = csub(u0, v);
            float2 v2 = cmul(u3, w3);
            dat[IX(q+h)]   = cadd(u1, v2);
            dat[IX(q+3*h)] = csub(u1, v2);
        }
        __syncthreads();
    }
    float* dst = d_outf + (size_t)row * NHW;
    const float sc = 1.0f / 16384.0f;
    for (int j = tid; j < 16384; j += 1024) {
        float2 v = dat[IX(j)];
        dst[j] = sqrtf(v.x*v.x + v.y*v.y) * sc;
    }
}

// ---------------- SE gate; d_work = g * xf (xf tile cached once) ----------------
__global__ void gate_kernel(const float* __restrict__ w1, const float* __restrict__ b1,
                            const float* __restrict__ bn_g, const float* __restrict__ bn_b,
                            const float* __restrict__ bn_m, const float* __restrict__ bn_v,
                            const float* __restrict__ w2, const float* __restrict__ b2) {
    extern __shared__ unsigned char s_raw[];
    float2* xc = (float2*)s_raw;              // [128][65]
    float* w1s = (float*)(xc + 128*65);       // [8][128]
    float* w2s = w1s + 1024;                  // [128][8]
    float* hid = w2s + 1024;                  // [8][65]
    int tid = threadIdx.x;
    int pp0 = blockIdx.x * 64;
    int b = pp0 >> 14, p0 = pp0 & (NHW-1);
    size_t sbase = (size_t)(b*128) * NHW + p0;
    for (int i = tid; i < 1024; i += 256) { w1s[i] = w1[i]; w2s[i] = w2[i]; }
    for (int i = tid; i < 8192; i += 256) {
        int cc = i >> 6, px = i & 63;
        xc[cc*65 + px] = d_xf[sbase + (size_t)cc * NHW + px];
    }
    __syncthreads();
    for (int t = tid; t < 512; t += 256) {
        int hc = t >> 6, px = t & 63;
        float h = b1[hc];
        #pragma unroll 8
        for (int cc = 0; cc < 128; ++cc) h += w1s[hc*128 + cc] * xc[cc*65 + px].x;
        h = (h - bn_m[hc]) * rsqrtf(bn_v[hc] + 1e-5f) * bn_g[hc] + bn_b[hc];
        hid[hc*65 + px] = fmaxf(h, 0.0f);
    }
    __syncthreads();
    for (int t = tid; t < 8192; t += 256) {
        int oc = t >> 6, px = t & 63;
        float sv = b2[oc];
        #pragma unroll
        for (int hc = 0; hc < 8; ++hc) sv += w2s[oc*8 + hc] * hid[hc*65 + px];
        float gg = 1.0f / (1.0f + expf(-sv));
        float2 xv = xc[oc*65 + px];
        d_work[sbase + (size_t)oc * NHW + px] = make_float2(gg*xv.x, gg*xv.y);
    }
}

// ---------------- 1x1 conv (128->128, bias), FFMA2 packed over oc pairs ----------------
__global__ void conv1x1_kernel(const float* __restrict__ in, const float* __restrict__ w,
                               const float* __restrict__ bias, float* __restrict__ out) {
    extern __shared__ unsigned char s_raw[];
    float* wt = (float*)s_raw;        // [128 ic][134]  (oc fast, transposed)
    float* xs = wt + 128*134;         // [128 ic][68]
    int tid = threadIdx.x;
    int pp0 = blockIdx.x * 64;
    int b = pp0 >> 14, p0 = pp0 & (NHW-1);
    for (int i = tid; i < 16384; i += 256) {
        int oc = i >> 7, ic = i & 127;
        wt[ic*134 + oc] = w[i];
    }
    for (int i = tid; i < 8192; i += 256) {
        int cc = i >> 6, px = i & 63;
        xs[cc*68 + px] = in[(size_t)(b*128 + cc) * NHW + p0 + px];
    }
    __syncthreads();
    int ocg = tid >> 4, pxg = tid & 15;
    int ocb = ocg * 8;
    unsigned long long acc2[4][4];
    #pragma unroll
    for (int p = 0; p < 4; ++p) {
        unsigned long long bp = pk2(bias[ocb + 2*p], bias[ocb + 2*p + 1]);
        #pragma unroll
        for (int v = 0; v < 4; ++v) acc2[p][v] = bp;
    }
    #pragma unroll 4
    for (int i = 0; i < 128; ++i) {
        float4 xv = *(const float4*)&xs[i*68 + pxg*4];
        unsigned long long xd0 = pk2(xv.x, xv.x);
        unsigned long long xd1 = pk2(xv.y, xv.y);
        unsigned long long xd2 = pk2(xv.z, xv.z);
        unsigned long long xd3 = pk2(xv.w, xv.w);
        const float* wrow = &wt[i*134 + ocb];
        #pragma unroll
        for (int p = 0; p < 4; ++p) {
            unsigned long long w2 = *(const unsigned long long*)&wrow[2*p];
            ffma2(acc2[p][0], w2, xd0);
            ffma2(acc2[p][1], w2, xd1);
            ffma2(acc2[p][2], w2, xd2);
            ffma2(acc2[p][3], w2, xd3);
        }
    }
    #pragma unroll
    for (int p = 0; p < 4; ++p) {
        float2 a0 = upk2(acc2[p][0]), a1 = upk2(acc2[p][1]);
        float2 a2 = upk2(acc2[p][2]), a3 = upk2(acc2[p][3]);
        int oc = ocb + 2*p;
        *(float4*)&out[(size_t)(b*128 + oc    ) * NHW + p0 + pxg*4] = make_float4(a0.x, a1.x, a2.x, a3.x);
        *(float4*)&out[(size_t)(b*128 + oc + 1) * NHW + p0 + pxg*4] = make_float4(a0.y, a1.y, a2.y, a3.y);
    }
}

// ------- grouped conv3 + conv5 (concat): 32x32 tile, FFMA2, packed weights -------
__global__ void gconv_kernel(const float* __restrict__ in, const float* __restrict__ w3,
                             const float* __restrict__ w5, float* __restrict__ out) {
    __shared__ float t0[36*40], t1[36*40];             // halo tiles, pitch 40 (16B aligned rows)
    __shared__ unsigned long long wp3[2][9], wp5[2][25]; // packed (w,w)
    int tid = threadIdx.x;
    int tile = blockIdx.x, g = blockIdx.y, b = blockIdx.z;
    int ty0 = (tile >> 2) * 32, tx0 = (tile & 3) * 32;
    const float* in0 = in + (size_t)(b*128 + 2*g) * NHW;
    const float* in1 = in0 + NHW;
    for (int i = tid; i < 1296; i += 256) {
        int ly = i / 36, lx = i % 36;
        int gy = ty0 - 2 + ly, gx = tx0 - 2 + lx;
        bool ok = ((unsigned)gy < 128u) && ((unsigned)gx < 128u);
        t0[ly*40 + lx] = ok ? in0[gy*128 + gx] : 0.f;
        t1[ly*40 + lx] = ok ? in1[gy*128 + gx] : 0.f;
    }
    if (tid < 18) {
        int ch = tid / 9, k = tid % 9;
        float w = w3[(g*2 + ch)*9 + k];
        wp3[ch][k] = pk2(w, w);
    } else if (tid >= 32 && tid < 82) {
        int t2 = tid - 32;
        int ch = t2 / 25, k = t2 % 25;
        float w = w5[(g*2 + ch)*25 + k];
        wp5[ch][k] = pk2(w, w);
    }
    __syncthreads();
    int ty = tid >> 3;             // 0..31
    int tx = (tid & 7) * 4;        // 0,4,...,28
    unsigned long long a3q0 = 0ULL, a3q1 = 0ULL, a5q0 = 0ULL, a5q1 = 0ULL;
    #pragma unroll
    for (int ch = 0; ch < 2; ++ch) {
        const float* t = ch ? t1 : t0;
        #pragma unroll
        for (int ky = 0; ky < 5; ++ky) {
            const float* row = &t[(ty + ky)*40 + tx];
            float4 rA = *(const float4*)row;
            float4 rB = *(const float4*)(row + 4);
            float r0 = rA.x, r1 = rA.y, r2 = rA.z, r3 = rA.w;
            float r4 = rB.x, r5 = rB.y, r6 = rB.z, r7 = rB.w;
            unsigned long long p0 = pk2(r0, r1), p1 = pk2(r1, r2), p2 = pk2(r2, r3);
            unsigned long long p3 = pk2(r3, r4), p4 = pk2(r4, r5), p5 = pk2(r5, r6);
            unsigned long long p6 = pk2(r6, r7);
            unsigned long long pr[7] = { p0, p1, p2, p3, p4, p5, p6 };
            #pragma unroll
            for (int kx = 0; kx < 5; ++kx) {
                unsigned long long w = wp5[ch][ky*5 + kx];
                ffma2(a5q0, w, pr[kx]);
                ffma2(a5q1, w, pr[kx + 2]);
            }
            if (ky >= 1 && ky <= 3) {
                #pragma unroll
                for (int kx = 0; kx < 3; ++kx) {
                    unsigned long long w = wp3[ch][(ky - 1)*3 + kx];
                    ffma2(a3q0, w, pr[1 + kx]);
                    ffma2(a3q1, w, pr[3 + kx]);
                }
            }
        }
    }
    int py = ty0 + ty, px = tx0 + tx;
    float2 a30 = upk2(a3q0), a31 = upk2(a3q1);
    float2 a50 = upk2(a5q0), a51 = upk2(a5q1);
    *(float4*)&out[(size_t)(b*128 + g)      * NHW + py*128 + px] = make_float4(a30.x, a30.y, a31.x, a31.y);
    *(float4*)&out[(size_t)(b*128 + 64 + g) * NHW + py*128 + px] = make_float4(a50.x, a50.y, a51.x, a51.y);
}

// ---------------- gram S partials (float4 loads, pitch 516) ----------------
__global__ void gram_s_part_kernel() {
    extern __shared__ unsigned char s_raw[];
    float* sq = (float*)s_raw;           // [16][516]
    float* sk = sq + 16*516;             // [16][516]
    int bh = blockIdx.x;
    int ns = blockIdx.y;
    int tid = threadIdx.x;
    int c = tid >> 4, d = tid & 15;
    const float* qb = d_q + (size_t)bh * HD * NHW + ns * (NHW / NS);
    const float* kb = d_k + (size_t)bh * HD * NHW + ns * (NHW / NS);
    float acc = 0.f, nq = 0.f, nk = 0.f;
    for (int ch = 0; ch < NHW / NS; ch += 512) {
        for (int i = tid; i < 8192; i += 256) {
            int hh = i >> 9, j = i & 511;
            sq[hh*516 + j] = qb[(size_t)hh*NHW + ch + j];
            sk[hh*516 + j] = kb[(size_t)hh*NHW + ch + j];
        }
        __syncthreads();
        #pragma unroll 4
        for (int j = 0; j < 512; j += 4) {
            float4 A = *(const float4*)&sq[c*516 + j];
            float4 B = *(const float4*)&sk[d*516 + j];
            acc += A.x*B.x + A.y*B.y + A.z*B.z + A.w*B.w;
            if (c == d) {
                nq += A.x*A.x + A.y*A.y + A.z*A.z + A.w*A.w;
                nk += B.x*B.x + B.y*B.y + B.z*B.z + B.w*B.w;
            }
        }
        __syncthreads();
    }
    int part = bh * NS + ns;
    d_gsp[part*256 + tid] = acc;
    if (c == d) { d_gsq[part*16 + c] = nq; d_gsk[part*16 + c] = nk; }
}

// ---------------- gram S finalize ----------------
__global__ void attns_finalize_kernel(const float* __restrict__ temp_s) {
    __shared__ float snq[16], snk[16];
    __shared__ float sA[16][17];
    int bh = blockIdx.x;
    int tid = threadIdx.x;
    int c = tid >> 4, d = tid & 15;
    float acc = 0.f;
    #pragma unroll
    for (int ns = 0; ns < NS; ++ns) acc += d_gsp[(bh*NS + ns)*256 + tid];
    if (tid < 16) {
        float nq = 0.f, nk = 0.f;
        #pragma unroll
        for (int ns = 0; ns < NS; ++ns) {
            nq += d_gsq[(bh*NS + ns)*16 + tid];
            nk += d_gsk[(bh*NS + ns)*16 + tid];
        }
        snq[tid] = fmaxf(sqrtf(nq), 1e-12f);
        snk[tid] = fmaxf(sqrtf(nk), 1e-12f);
    }
    __syncthreads();
    sA[c][d] = acc * temp_s[bh & 7] / (snq[c] * snk[d]);
    __syncthreads();
    if (tid < 16) {
        int row = tid;
        float m = -1e30f;
        #pragma unroll
        for (int dd = 0; dd < 16; ++dd) m = fmaxf(m, sA[row][dd]);
        float e[16], s = 0.f;
        #pragma unroll
        for (int dd = 0; dd < 16; ++dd) { e[dd] = expf(sA[row][dd] - m); s += e[dd]; }
        float is = 1.f / s;
        #pragma unroll
        for (int dd = 0; dd < 16; ++dd) d_attns[bh*256 + row*16 + dd] = e[dd] * is;
    }
}

// ---------------- out_s = attn_s @ v -> d_bufT (FFMA2 over cc pairs) ----------------
__global__ void __launch_bounds__(256, 4) apply_attn_s_kernel() {
    __shared__ ulonglong2 At[64];   // [dd][pq]: pq covers cc pairs (4pq..4pq+3)
    int bh = blockIdx.x, nb = blockIdx.y;
    int tid = threadIdx.x;
    if (tid < 64) {
        int dd = tid >> 2, pq = tid & 3;
        const float* Ab = d_attns + bh*256;
        At[tid] = make_ulonglong2(
            pk2(Ab[(4*pq    )*16 + dd], Ab[(4*pq + 1)*16 + dd]),
            pk2(Ab[(4*pq + 2)*16 + dd], Ab[(4*pq + 3)*16 + dd]));
    }
    __syncthreads();
    int n = nb*256 + tid;
    const float* vb = d_v + (size_t)bh * HD * NHW + n;
    unsigned long long o2[8];
    #pragma unroll
    for (int p = 0; p < 8; ++p) o2[p] = 0ULL;
    #pragma unroll
    for (int dd = 0; dd < 16; ++dd) {
        float vv = vb[(size_t)dd * NHW];
        unsigned long long vd = pk2(vv, vv);
        #pragma unroll
        for (int pq = 0; pq < 4; ++pq) {
            ulonglong2 ap = At[dd*4 + pq];
            ffma2(o2[pq*2    ], ap.x, vd);
            ffma2(o2[pq*2 + 1], ap.y, vd);
        }
    }
    float* dst = d_bufT + (size_t)bh * HD * NHW + n;
    #pragma unroll
    for (int p = 0; p < 8; ++p) {
        float2 o = upk2(o2[p]);
        dst[(size_t)(2*p    ) * NHW] = o.x;
        dst[(size_t)(2*p + 1) * NHW] = o.y;
    }
}

// ---------------- final fused projection (fsa + ssa), FFMA2 ----------------
__global__ void final_conv_kernel(const float* __restrict__ pfw, const float* __restrict__ psw,
                                  float* __restrict__ out) {
    extern __shared__ unsigned char s_raw[];
    float* wt = (float*)s_raw;        // [128 ic][134]
    float* xs = wt + 128*134;         // [128 ic][68]
    int tid = threadIdx.x;
    int pp0 = blockIdx.x * 64;
    int b = pp0 >> 14, p0 = pp0 & (NHW-1);
    int ocg = tid >> 4, pxg = tid & 15;
    int ocb = ocg * 8;
    unsigned long long acc2[4][4];
    #pragma unroll
    for (int p = 0; p < 4; ++p)
        #pragma unroll
        for (int v = 0; v < 4; ++v) acc2[p][v] = 0ULL;
    const float* ins[4] = { d_outf, d_outfl, d_bufT, d_outsl };
    for (int pass = 0; pass < 4; ++pass) {
        const float* wsrc = (pass < 2) ? pfw : psw;
        int off = (pass & 1) * 128;
        for (int i = tid; i < 16384; i += 256) {
            int oc = i >> 7, ic = i & 127;
            wt[ic*134 + oc] = wsrc[oc*256 + off + ic];
        }
        const float* in = ins[pass];
        for (int i = tid; i < 8192; i += 256) {
            int cc = i >> 6, px = i & 63;
            xs[cc*68 + px] = in[(size_t)(b*128 + cc) * NHW + p0 + px];
        }
        __syncthreads();
        #pragma unroll 4
        for (int i = 0; i < 128; ++i) {
            float4 xv = *(const float4*)&xs[i*68 + pxg*4];
            unsigned long long xd0 = pk2(xv.x, xv.x);
            unsigned long long xd1 = pk2(xv.y, xv.y);
            unsigned long long xd2 = pk2(xv.z, xv.z);
            unsigned long long xd3 = pk2(xv.w, xv.w);
            const float* wrow = &wt[i*134 + ocb];
            #pragma unroll
            for (int p = 0; p < 4; ++p) {
                unsigned long long w2 = *(const unsigned long long*)&wrow[2*p];
                ffma2(acc2[p][0], w2, xd0);
                ffma2(acc2[p][1], w2, xd1);
                ffma2(acc2[p][2], w2, xd2);
                ffma2(acc2[p][3], w2, xd3);
            }
        }
        __syncthreads();
    }
    #pragma unroll
    for (int p = 0; p < 4; ++p) {
        float2 a0 = upk2(acc2[p][0]), a1 = upk2(acc2[p][1]);
        float2 a2 = upk2(acc2[p][2]), a3 = upk2(acc2[p][3]);
        int oc = ocb + 2*p;
        *(float4*)&out[(size_t)(b*128 + oc    ) * NHW + p0 + pxg*4] = make_float4(a0.x, a1.x, a2.x, a3.x);
        *(float4*)&out[(size_t)(b*128 + oc + 1) * NHW + p0 + pxg*4] = make_float4(a0.y, a1.y, a2.y, a3.y);
    }
}

// ---------------- host launcher ----------------
#define SM_FFT2  ((128*FPITCH + 64) * (int)sizeof(float2))      // 132,608
#define SM_ROW   ((16896 + 8192) * (int)sizeof(float2))         // 200,704
#define SM_GRAMF (16*514 * (int)sizeof(float2))                 //  65,792
#define SM_GRAMS (2*16*516 * (int)sizeof(float))                //  66,048
#define SM_CONV  ((128*134 + 128*68) * (int)sizeof(float))      // 103,424
#define SM_GATE  ((128*65) * (int)sizeof(float2) + (1024 + 1024 + 8*65) * (int)sizeof(float))

extern "C" void kernel_launch(void* const* d_in, const int* in_sizes, int n_in,
                              void* d_out, int out_size) {
    (void)in_sizes; (void)n_in; (void)out_size;
    const float* x       = (const float*)d_in[0];
    const float* temp_f  = (const float*)d_in[1];
    const float* w1      = (const float*)d_in[2];
    const float* b1      = (const float*)d_in[3];
    const float* bn_g    = (const float*)d_in[4];
    const float* bn_b    = (const float*)d_in[5];
    const float* bn_m    = (const float*)d_in[6];
    const float* bn_v    = (const float*)d_in[7];
    const float* w2      = (const float*)d_in[8];
    const float* b2      = (const float*)d_in[9];
    const float* projf_w = (const float*)d_in[10];
    const float* temp_s  = (const float*)d_in[11];
    const float* q1_w = (const float*)d_in[12];
    const float* q1_b = (const float*)d_in[13];
    const float* k1_w = (const float*)d_in[14];
    const float* k1_b = (const float*)d_in[15];
    const float* v1_w = (const float*)d_in[16];
    const float* v1_b = (const float*)d_in[17];
    const float* q3_w = (const float*)d_in[18];
    const float* q5_w = (const float*)d_in[19];
    const float* k3_w = (const float*)d_in[20];
    const float* k5_w = (const float*)d_in[21];
    const float* v3_w = (const float*)d_in[22];
    const float* v5_w = (const float*)d_in[23];
    const float* c3_w = (const float*)d_in[24];
    const float* c5_w = (const float*)d_in[25];
    const float* projs_w = (const float*)d_in[26];
    float* out = (float*)d_out;

    cudaFuncSetAttribute(fft2_fwd_kernel,    cudaFuncAttributeMaxDynamicSharedMemorySize, SM_FFT2);
    cudaFuncSetAttribute(ifft2_abs_kernel,   cudaFuncAttributeMaxDynamicSharedMemorySize, SM_FFT2);
    cudaFuncSetAttribute(ifft_row_kernel,    cudaFuncAttributeMaxDynamicSharedMemorySize, SM_ROW);
    cudaFuncSetAttribute(gram_f_part_kernel, cudaFuncAttributeMaxDynamicSharedMemorySize, SM_GRAMF);
    cudaFuncSetAttribute(gram_s_part_kernel, cudaFuncAttributeMaxDynamicSharedMemorySize, SM_GRAMS);
    cudaFuncSetAttribute(conv1x1_kernel,     cudaFuncAttributeMaxDynamicSharedMemorySize, SM_CONV);
    cudaFuncSetAttribute(final_conv_kernel,  cudaFuncAttributeMaxDynamicSharedMemorySize, SM_CONV);
    cudaFuncSetAttribute(gate_kernel,        cudaFuncAttributeMaxDynamicSharedMemorySize, SM_GATE);

    float *pT, *pQ, *pK, *pV, *pSL, *ptq, *ptk;
    cudaGetSymbolAddress((void**)&pT,  d_bufT);
    cudaGetSymbolAddress((void**)&pQ,  d_q);
    cudaGetSymbolAddress((void**)&pK,  d_k);
    cudaGetSymbolAddress((void**)&pV,  d_v);
    cudaGetSymbolAddress((void**)&pSL, d_outsl);
    cudaGetSymbolAddress((void**)&ptq, d_tq);
    cudaGetSymbolAddress((void**)&ptk, d_tk);
    float* tq = ptq;     // dedicated scratch (no overlay with freq branch)
    float* tk = ptk;
    float* tv = pT;      // d_bufT is spatial-branch-only

    // One-time creation of the fork stream + events (resource init only; the
    // launched work is identical on every call).
    static cudaStream_t s_sp = nullptr;
    static cudaEvent_t ev_fork = nullptr, ev_join = nullptr;
    if (s_sp == nullptr) {
        cudaStreamCreateWithFlags(&s_sp, cudaStreamNonBlocking);
        cudaEventCreateWithFlags(&ev_fork, cudaEventDisableTiming);
        cudaEventCreateWithFlags(&ev_join, cudaEventDisableTiming);
    }

    // ---- fork: spatial branch runs on s_sp concurrently with freq branch ----
    cudaEventRecord(ev_fork, 0);
    cudaStreamWaitEvent(s_sp, ev_fork, 0);

    // ---- spatial branch (stream s_sp) ----
    conv1x1_kernel<<<2048, 256, SM_CONV, s_sp>>>(x, q1_w, q1_b, tq);
    gconv_kernel<<<dim3(16, 64, 8), 256, 0, s_sp>>>(tq, q3_w, q5_w, pQ);
    conv1x1_kernel<<<2048, 256, SM_CONV, s_sp>>>(x, k1_w, k1_b, tk);
    gconv_kernel<<<dim3(16, 64, 8), 256, 0, s_sp>>>(tk, k3_w, k5_w, pK);
    conv1x1_kernel<<<2048, 256, SM_CONV, s_sp>>>(x, v1_w, v1_b, tv);
    gconv_kernel<<<dim3(16, 64, 8), 256, 0, s_sp>>>(tv, v3_w, v5_w, pV);
    gconv_kernel<<<dim3(16, 64, 8), 256, 0, s_sp>>>(x, c3_w, c5_w, pSL);
    gram_s_part_kernel<<<dim3(64, NS), 256, SM_GRAMS, s_sp>>>();
    attns_finalize_kernel<<<64, 256, 0, s_sp>>>(temp_s);
    apply_attn_s_kernel<<<dim3(64, 64), 256, 0, s_sp>>>();   // writes d_bufT (out_s)

    // ---- frequency branch (capture/legacy stream) ----
    fft2_fwd_kernel<<<1024, 512, SM_FFT2>>>(x);
    gram_f_part_kernel<<<dim3(64, NS), 256, SM_GRAMF>>>();
    attnf_finalize_kernel<<<64, 256>>>(temp_f);
    apply_attn_f_kernel<<<dim3(64, 64), 256>>>();   // fused with ifft16
    ifft_row_kernel<<<1024, 1024, SM_ROW>>>();
    gate_kernel<<<2048, 256, SM_GATE>>>(w1, b1, bn_g, bn_b, bn_m, bn_v, w2, b2);
    ifft2_abs_kernel<<<1024, 512, SM_FFT2>>>();

    // ---- join: final projection needs both branches ----
    cudaEventRecord(ev_join, s_sp);
    cudaStreamWaitEvent(0, ev_join, 0);
    final_conv_kernel<<<2048, 256, SM_CONV>>>(projf_w, projs_w, out);
}

// round 15
// speedup vs baseline: 1.1657x; 1.0057x over previous
#include <cuda_runtime.h>
#include <cstdint>

// ---------------- problem constants ----------------
#define NB     8
#define NC     128
#define NHW    16384            // 128*128
#define NHEADS 8
#define HD     16               // head dim (channels per head)
#define NELEM  16777216         // NB*NC*NHW
#define NS     16               // gram n-split

#define FPITCH 129              // 128x128 fft tile pitch (float2)

// ---------------- scratch (device globals; no allocs allowed) ----------------
__device__ float2 d_xf[NELEM];      // fft2(x)
__device__ float2 d_work[NELEM];    // out_cplx (applyF -> ifft_row)
__device__ float2 d_work2[NELEM];   // g*xf     (gate -> ifft2_abs)
__device__ float  d_outf[NELEM];    // |ifft2(out_cplx)|
__device__ float  d_outfl[NELEM];   // |ifft2(g*xf)|
__device__ float  d_q[NELEM];
__device__ float  d_k[NELEM];
__device__ float  d_v[NELEM];
__device__ float  d_outsl[NELEM];
__device__ float  d_bufT[NELEM];    // v-temp, then out_s (spatial)
__device__ float  d_tq[NELEM];      // q-temp
__device__ float  d_tk[NELEM];      // k-temp
__device__ float2 d_attnf[NB*NHEADS*HD*HD];
__device__ float  d_attns[NB*NHEADS*HD*HD];
// gram partials
__device__ float2 d_gfp[NB*NHEADS*NS*256];
__device__ float  d_gfn[NB*NHEADS*NS*16];
__device__ float  d_gsp[NB*NHEADS*NS*256];
__device__ float  d_gsq[NB*NHEADS*NS*16];
__device__ float  d_gsk[NB*NHEADS*NS*16];

// ---------------- helpers ----------------
__device__ __forceinline__ float2 cmul(float2 a, float2 b) {
    return make_float2(a.x*b.x - a.y*b.y, a.x*b.y + a.y*b.x);
}
__device__ __forceinline__ float2 cadd(float2 a, float2 b) { return make_float2(a.x+b.x, a.y+b.y); }
__device__ __forceinline__ float2 csub(float2 a, float2 b) { return make_float2(a.x-b.x, a.y-b.y); }
__device__ __forceinline__ int brev7(int v) { return __brev(v) >> 25; }

// ---- packed fp32x2 (Blackwell FFMA2 path) ----
__device__ __forceinline__ unsigned long long pk2(float a, float b) {
    unsigned long long r;
    asm("mov.b64 %0, {%1, %2};" : "=l"(r) : "f"(a), "f"(b));
    return r;
}
__device__ __forceinline__ void ffma2(unsigned long long& c, unsigned long long a, unsigned long long b) {
    asm("fma.rn.f32x2 %0, %1, %2, %0;" : "+l"(c) : "l"(a), "l"(b));
}
__device__ __forceinline__ float2 upk2(unsigned long long v) {
    float2 r;
    asm("mov.b64 {%0, %1}, %2;" : "=f"(r.x), "=f"(r.y) : "l"(v));
    return r;
}

// ============ 2D 128x128 FFT (radix-2^2), input loaded bit-reversed ============
template <int NT>
__device__ void fft2_128_r4(float2* s, const float2* tw, int tid) {
    #pragma unroll
    for (int st = 0; st < 6; st += 2) {
        int h = 1 << st;
        for (int idx = tid; idx < 4096; idx += NT) {
            int r = idx & 127, j = idx >> 7;      // j in [0,32)
            int pos = j & (h - 1);
            int q = ((j >> st) << (st + 2)) + pos;
            float2* row = s + r * FPITCH;
            float2 a = row[q], b = row[q+h], c = row[q+2*h], d = row[q+3*h];
            float2 w1 = tw[pos << (6 - st)];
            float2 t  = cmul(b, w1);
            float2 u0 = cadd(a, t), u1 = csub(a, t);
            float2 t2 = cmul(d, w1);
            float2 u2 = cadd(c, t2), u3 = csub(c, t2);
            float2 w2 = tw[pos << (5 - st)];
            float2 w3 = tw[(pos + h) << (5 - st)];
            float2 v  = cmul(u2, w2);
            row[q]       = cadd(u0, v);
            row[q+2*h]   = csub(u0, v);
            float2 v2 = cmul(u3, w3);
            row[q+h]     = cadd(u1, v2);
            row[q+3*h]   = csub(u1, v2);
        }
        __syncthreads();
    }
    for (int idx = tid; idx < 8192; idx += NT) {
        int r = idx & 127, pos = idx >> 7;        // pos in [0,64)
        float2 w = tw[pos];
        float2* p0 = &s[r*FPITCH + pos];
        float2* p1 = &s[r*FPITCH + pos + 64];
        float2 a = *p0, t = cmul(*p1, w);
        *p0 = cadd(a, t);
        *p1 = csub(a, t);
    }
    __syncthreads();
    #pragma unroll
    for (int st = 0; st < 6; st += 2) {
        int h = 1 << st;
        for (int idx = tid; idx < 4096; idx += NT) {
            int c0 = idx & 127, j = idx >> 7;
            int pos = j & (h - 1);
            int q = ((j >> st) << (st + 2)) + pos;
            float2 a = s[(q      )*FPITCH + c0];
            float2 b = s[(q +   h)*FPITCH + c0];
            float2 c = s[(q + 2*h)*FPITCH + c0];
            float2 d = s[(q + 3*h)*FPITCH + c0];
            float2 w1 = tw[pos << (6 - st)];
            float2 t  = cmul(b, w1);
            float2 u0 = cadd(a, t), u1 = csub(a, t);
            float2 t2 = cmul(d, w1);
            float2 u2 = cadd(c, t2), u3 = csub(c, t2);
            float2 w2 = tw[pos << (5 - st)];
            float2 w3 = tw[(pos + h) << (5 - st)];
            float2 v  = cmul(u2, w2);
            s[(q      )*FPITCH + c0] = cadd(u0, v);
            s[(q + 2*h)*FPITCH + c0] = csub(u0, v);
            float2 v2 = cmul(u3, w3);
            s[(q +   h)*FPITCH + c0] = cadd(u1, v2);
            s[(q + 3*h)*FPITCH + c0] = csub(u1, v2);
        }
        __syncthreads();
    }
    for (int idx = tid; idx < 8192; idx += NT) {
        int c0 = idx & 127, pos = idx >> 7;
        float2 w = tw[pos];
        float2* p0 = &s[pos*FPITCH + c0];
        float2* p1 = &s[(pos + 64)*FPITCH + c0];
        float2 a = *p0, t = cmul(*p1, w);
        *p0 = cadd(a, t);
        *p1 = csub(a, t);
    }
    __syncthreads();
}

// ---------------- forward FFT2 of x -> d_xf ----------------
__global__ void fft2_fwd_kernel(const float* __restrict__ x) {
    extern __shared__ unsigned char s_raw[];
    float2* s = (float2*)s_raw;
    float2* tw = s + 128*FPITCH;
    int tid = threadIdx.x;  // 512
    int slice = blockIdx.x; // b*128 + c
    if (tid < 64) {
        float sv, cv; sincospif(-(float)tid * (1.0f/64.0f), &sv, &cv);
        tw[tid] = make_float2(cv, sv);
    }
    const float* xin = x + (size_t)slice * NHW;
    for (int idx = tid; idx < 16384; idx += 512) {
        int r = idx >> 7, c = idx & 127;
        s[brev7(r)*FPITCH + brev7(c)] = make_float2(xin[idx], 0.0f);
    }
    __syncthreads();
    fft2_128_r4<512>(s, tw, tid);
    float2* dst = d_xf + (size_t)slice * NHW;
    for (int idx = tid; idx < 16384; idx += 512) {
        int r = idx >> 7, c = idx & 127;
        dst[idx] = s[r*FPITCH + c];
    }
}

// ---------------- inverse FFT2 + abs of d_work2 -> d_outfl ----------------
__global__ void ifft2_abs_kernel() {
    extern __shared__ unsigned char s_raw[];
    float2* s = (float2*)s_raw;
    float2* tw = s + 128*FPITCH;
    int tid = threadIdx.x;  // 512
    int slice = blockIdx.x;
    if (tid < 64) {
        float sv, cv; sincospif((float)tid * (1.0f/64.0f), &sv, &cv);
        tw[tid] = make_float2(cv, sv);
    }
    const float2* xin = d_work2 + (size_t)slice * NHW;
    for (int idx = tid; idx < 16384; idx += 512) {
        int r = idx >> 7, c = idx & 127;
        s[brev7(r)*FPITCH + brev7(c)] = xin[idx];
    }
    __syncthreads();
    fft2_128_r4<512>(s, tw, tid);
    float* dst = d_outfl + (size_t)slice * NHW;
    const float sc = 1.0f / 16384.0f;
    for (int idx = tid; idx < 16384; idx += 512) {
        int r = idx >> 7, c = idx & 127;
        float2 v = s[r*FPITCH + c];
        dst[idx] = sqrtf(v.x*v.x + v.y*v.y) * sc;
    }
}

// ---------------- gram F partials (float4 loads, pitch 514) ----------------
__global__ void gram_f_part_kernel() {
    extern __shared__ unsigned char s_raw[];
    float2* sq = (float2*)s_raw;      // [16][514]
    int bh = blockIdx.x;              // b*8 + head
    int ns = blockIdx.y;              // n-chunk
    int tid = threadIdx.x;
    int c = tid >> 4, d = tid & 15;
    float2 acc = make_float2(0.f, 0.f);
    float nrm = 0.f;
    const float2* base = d_xf + (size_t)bh * HD * NHW + ns * (NHW / NS);
    for (int ch = 0; ch < NHW / NS; ch += 512) {
        for (int i = tid; i < 8192; i += 256) {
            int hh = i >> 9, j = i & 511;
            sq[hh*514 + j] = base[(size_t)hh*NHW + ch + j];
        }
        __syncthreads();
        #pragma unroll 4
        for (int j = 0; j < 512; j += 2) {
            float4 A = *(const float4*)&sq[c*514 + j];
            float4 B = *(const float4*)&sq[d*514 + j];
            acc.x += A.x*B.x - A.y*B.y;
            acc.y += A.x*B.y + A.y*B.x;
            acc.x += A.z*B.z - A.w*B.w;
            acc.y += A.z*B.w + A.w*B.z;
            if (c == d) nrm += A.x*A.x + A.y*A.y + A.z*A.z + A.w*A.w;
        }
        __syncthreads();
    }
    int part = bh * NS + ns;
    d_gfp[part*256 + tid] = acc;
    if (c == d) d_gfn[part*16 + c] = nrm;
}

// ---------------- gram F finalize ----------------
__global__ void attnf_finalize_kernel(const float* __restrict__ temp_f) {
    __shared__ float  snrm[16];
    __shared__ float2 sA[16][17];
    int bh = blockIdx.x;
    int tid = threadIdx.x;
    int c = tid >> 4, d = tid & 15;
    float2 acc = make_float2(0.f, 0.f);
    #pragma unroll
    for (int ns = 0; ns < NS; ++ns) {
        float2 p = d_gfp[(bh*NS + ns)*256 + tid];
        acc.x += p.x; acc.y += p.y;
    }
    if (tid < 16) {
        float nrm = 0.f;
        #pragma unroll
        for (int ns = 0; ns < NS; ++ns) nrm += d_gfn[(bh*NS + ns)*16 + tid];
        snrm[tid] = fmaxf(sqrtf(nrm), 1e-12f);
    }
    __syncthreads();
    float tf = temp_f[bh & 7];
    float inv = tf / (snrm[c] * snrm[d]);
    sA[c][d] = make_float2(acc.x * inv, acc.y * inv);
    __syncthreads();
    if (tid < 16) {
        int row = tid;
        float mr = -1e30f, mi = -1e30f;
        #pragma unroll
        for (int dd = 0; dd < 16; ++dd) {
            mr = fmaxf(mr, sA[row][dd].x);
            mi = fmaxf(mi, sA[row][dd].y);
        }
        float er[16], ei[16], sr = 0.f, si = 0.f;
        #pragma unroll
        for (int dd = 0; dd < 16; ++dd) {
            er[dd] = expf(sA[row][dd].x - mr);
            ei[dd] = expf(sA[row][dd].y - mi);
            sr += er[dd]; si += ei[dd];
        }
        float isr = 1.f/sr, isi = 1.f/si;
        #pragma unroll
        for (int dd = 0; dd < 16; ++dd)
            d_attnf[bh*256 + row*16 + dd] = make_float2(er[dd]*isr, ei[dd]*isi);
    }
}

// ------- out_cplx = attn_f @ qf, fused with IFFT-16 along hd (scalar R5 form) -------
__global__ void __launch_bounds__(256, 4) apply_attn_f_kernel() {
    __shared__ float2 A[256];
    int bh = blockIdx.x, nb = blockIdx.y;
    int tid = threadIdx.x;
    A[tid] = d_attnf[bh*256 + tid];
    __syncthreads();
    int n = nb*256 + tid;
    const float2* src = d_xf + (size_t)bh * HD * NHW + n;
    float2 o[16];
    #pragma unroll
    for (int cc = 0; cc < 16; ++cc) o[cc] = make_float2(0.f, 0.f);
    #pragma unroll
    for (int dd = 0; dd < 16; ++dd) {
        float2 qv = src[(size_t)dd * NHW];
        #pragma unroll
        for (int cc = 0; cc < 16; ++cc) {
            float2 a = A[cc*16 + dd];
            o[cc].x += a.x*qv.x - a.y*qv.y;
            o[cc].y += a.x*qv.y + a.y*qv.x;
        }
    }
    const int BR[16] = {0,8,4,12,2,10,6,14,1,9,5,13,3,11,7,15};
    float2 y[16];
    #pragma unroll
    for (int j = 0; j < 16; ++j) y[BR[j]] = o[j];
    const float C1 = 0.9238795325112867f, S1 = 0.3826834323650898f, R2 = 0.7071067811865476f;
    const float2 W[8] = {{1.f,0.f},{C1,S1},{R2,R2},{S1,C1},{0.f,1.f},{-S1,C1},{-R2,R2},{-C1,S1}};
    #pragma unroll
    for (int st = 0; st < 4; ++st) {
        int half = 1 << st;
        #pragma unroll
        for (int j = 0; j < 8; ++j) {
            int pos = j & (half - 1);
            int b2 = ((j >> st) << (st + 1)) + pos;
            float2 w = W[pos << (3 - st)];
            float2 a = y[b2];
            float2 t = cmul(y[b2 + half], w);
            y[b2]        = cadd(a, t);
            y[b2 + half] = csub(a, t);
        }
    }
    const float sc = 1.0f / 16.0f;
    float2* dst = d_work + (size_t)bh * HD * NHW + n;
    #pragma unroll
    for (int k = 0; k < 16; ++k)
        dst[(size_t)k * NHW] = make_float2(y[k].x*sc, y[k].y*sc);
}

// ---- 16384-point IFFT per row + abs -> d_outf (padded, table twiddles) ----
#define IX(i) ((i) + ((i) >> 5))
__global__ void ifft_row_kernel() {
    extern __shared__ unsigned char s_raw[];
    float2* dat = (float2*)s_raw;        // padded: 16896
    float2* tw  = dat + 16896;           // 8192
    __shared__ float2 hi[128], lo[64];
    int tid = threadIdx.x;               // 1024
    int row = blockIdx.x;                // b*128 + c
    if (tid < 128) {
        float sv, cv; sincospif((float)tid * (1.0f/128.0f), &sv, &cv);
        hi[tid] = make_float2(cv, sv);
    } else if (tid < 192) {
        int j = tid - 128;
        float sv, cv; sincospif((float)j * (1.0f/8192.0f), &sv, &cv);
        lo[j] = make_float2(cv, sv);
    }
    __syncthreads();
    for (int j = tid; j < 8192; j += 1024)
        tw[j] = cmul(hi[j >> 6], lo[j & 63]);
    const float2* src = d_work + (size_t)row * NHW;
    for (int j = tid; j < 16384; j += 1024) {
        int p = __brev(j) >> 18;
        dat[IX(p)] = src[j];
    }
    __syncthreads();
    #pragma unroll
    for (int st = 0; st < 14; st += 2) {
        int h = 1 << st;
        for (int idx = tid; idx < 4096; idx += 1024) {
            int pos = idx & (h - 1);
            int q = ((idx >> st) << (st + 2)) + pos;
            float2 a = dat[IX(q)], b = dat[IX(q+h)], c = dat[IX(q+2*h)], d = dat[IX(q+3*h)];
            float2 w1 = tw[pos << (13 - st)];
            float2 t  = cmul(b, w1);
            float2 u0 = cadd(a, t), u1 = csub(a, t);
            float2 t2 = cmul(d, w1);
            float2 u2 = cadd(c, t2), u3 = csub(c, t2);
            float2 w2 = tw[pos << (12 - st)];
            float2 w3 = tw[(pos + h) << (12 - st)];
            float2 v  = cmul(u2, w2);
            dat[IX(q)]     = cadd(u0, v);
            dat[IX(q+2*h)] = csub(u0, v);
            float2 v2 = cmul(u3, w3);
            dat[IX(q+h)]   = cadd(u1, v2);
            dat[IX(q+3*h)] = csub(u1, v2);
        }
        __syncthreads();
    }
    float* dst = d_outf + (size_t)row * NHW;
    const float sc = 1.0f / 16384.0f;
    for (int j = tid; j < 16384; j += 1024) {
        float2 v = dat[IX(j)];
        dst[j] = sqrtf(v.x*v.x + v.y*v.y) * sc;
    }
}

// ---------------- SE gate; d_work2 = g * xf (xf tile cached once) ----------------
__global__ void gate_kernel(const float* __restrict__ w1, const float* __restrict__ b1,
                            const float* __restrict__ bn_g, const float* __restrict__ bn_b,
                            const float* __restrict__ bn_m, const float* __restrict__ bn_v,
                            const float* __restrict__ w2, const float* __restrict__ b2) {
    extern __shared__ unsigned char s_raw[];
    float2* xc = (float2*)s_raw;              // [128][65]
    float* w1s = (float*)(xc + 128*65);       // [8][128]
    float* w2s = w1s + 1024;                  // [128][8]
    float* hid = w2s + 1024;                  // [8][65]
    int tid = threadIdx.x;
    int pp0 = blockIdx.x * 64;
    int b = pp0 >> 14, p0 = pp0 & (NHW-1);
    size_t sbase = (size_t)(b*128) * NHW + p0;
    for (int i = tid; i < 1024; i += 256) { w1s[i] = w1[i]; w2s[i] = w2[i]; }
    for (int i = tid; i < 8192; i += 256) {
        int cc = i >> 6, px = i & 63;
        xc[cc*65 + px] = d_xf[sbase + (size_t)cc * NHW + px];
    }
    __syncthreads();
    for (int t = tid; t < 512; t += 256) {
        int hc = t >> 6, px = t & 63;
        float h = b1[hc];
        #pragma unroll 8
        for (int cc = 0; cc < 128; ++cc) h += w1s[hc*128 + cc] * xc[cc*65 + px].x;
        h = (h - bn_m[hc]) * rsqrtf(bn_v[hc] + 1e-5f) * bn_g[hc] + bn_b[hc];
        hid[hc*65 + px] = fmaxf(h, 0.0f);
    }
    __syncthreads();
    for (int t = tid; t < 8192; t += 256) {
        int oc = t >> 6, px = t & 63;
        float sv = b2[oc];
        #pragma unroll
        for (int hc = 0; hc < 8; ++hc) sv += w2s[oc*8 + hc] * hid[hc*65 + px];
        float gg = 1.0f / (1.0f + expf(-sv));
        float2 xv = xc[oc*65 + px];
        d_work2[sbase + (size_t)oc * NHW + px] = make_float2(gg*xv.x, gg*xv.y);
    }
}

// ---------------- 1x1 conv (128->128, bias), FFMA2 packed over oc pairs ----------------
__global__ void conv1x1_kernel(const float* __restrict__ in, const float* __restrict__ w,
                               const float* __restrict__ bias, float* __restrict__ out) {
    extern __shared__ unsigned char s_raw[];
    float* wt = (float*)s_raw;        // [128 ic][134]  (oc fast, transposed)
    float* xs = wt + 128*134;         // [128 ic][68]
    int tid = threadIdx.x;
    int pp0 = blockIdx.x * 64;
    int b = pp0 >> 14, p0 = pp0 & (NHW-1);
    for (int i = tid; i < 16384; i += 256) {
        int oc = i >> 7, ic = i & 127;
        wt[ic*134 + oc] = w[i];
    }
    for (int i = tid; i < 8192; i += 256) {
        int cc = i >> 6, px = i & 63;
        xs[cc*68 + px] = in[(size_t)(b*128 + cc) * NHW + p0 + px];
    }
    __syncthreads();
    int ocg = tid >> 4, pxg = tid & 15;
    int ocb = ocg * 8;
    unsigned long long acc2[4][4];
    #pragma unroll
    for (int p = 0; p < 4; ++p) {
        unsigned long long bp = pk2(bias[ocb + 2*p], bias[ocb + 2*p + 1]);
        #pragma unroll
        for (int v = 0; v < 4; ++v) acc2[p][v] = bp;
    }
    #pragma unroll 4
    for (int i = 0; i < 128; ++i) {
        float4 xv = *(const float4*)&xs[i*68 + pxg*4];
        unsigned long long xd0 = pk2(xv.x, xv.x);
        unsigned long long xd1 = pk2(xv.y, xv.y);
        unsigned long long xd2 = pk2(xv.z, xv.z);
        unsigned long long xd3 = pk2(xv.w, xv.w);
        const float* wrow = &wt[i*134 + ocb];
        #pragma unroll
        for (int p = 0; p < 4; ++p) {
            unsigned long long w2 = *(const unsigned long long*)&wrow[2*p];
            ffma2(acc2[p][0], w2, xd0);
            ffma2(acc2[p][1], w2, xd1);
            ffma2(acc2[p][2], w2, xd2);
            ffma2(acc2[p][3], w2, xd3);
        }
    }
    #pragma unroll
    for (int p = 0; p < 4; ++p) {
        float2 a0 = upk2(acc2[p][0]), a1 = upk2(acc2[p][1]);
        float2 a2 = upk2(acc2[p][2]), a3 = upk2(acc2[p][3]);
        int oc = ocb + 2*p;
        *(float4*)&out[(size_t)(b*128 + oc    ) * NHW + p0 + pxg*4] = make_float4(a0.x, a1.x, a2.x, a3.x);
        *(float4*)&out[(size_t)(b*128 + oc + 1) * NHW + p0 + pxg*4] = make_float4(a0.y, a1.y, a2.y, a3.y);
    }
}

// ------- grouped conv3 + conv5 (concat): 32x32 tile, FFMA2, packed weights -------
__global__ void gconv_kernel(const float* __restrict__ in, const float* __restrict__ w3,
                             const float* __restrict__ w5, float* __restrict__ out) {
    __shared__ float t0[36*40], t1[36*40];             // halo tiles, pitch 40 (16B aligned rows)
    __shared__ unsigned long long wp3[2][9], wp5[2][25]; // packed (w,w)
    int tid = threadIdx.x;
    int tile = blockIdx.x, g = blockIdx.y, b = blockIdx.z;
    int ty0 = (tile >> 2) * 32, tx0 = (tile & 3) * 32;
    const float* in0 = in + (size_t)(b*128 + 2*g) * NHW;
    const float* in1 = in0 + NHW;
    for (int i = tid; i < 1296; i += 256) {
        int ly = i / 36, lx = i % 36;
        int gy = ty0 - 2 + ly, gx = tx0 - 2 + lx;
        bool ok = ((unsigned)gy < 128u) && ((unsigned)gx < 128u);
        t0[ly*40 + lx] = ok ? in0[gy*128 + gx] : 0.f;
        t1[ly*40 + lx] = ok ? in1[gy*128 + gx] : 0.f;
    }
    if (tid < 18) {
        int ch = tid / 9, k = tid % 9;
        float w = w3[(g*2 + ch)*9 + k];
        wp3[ch][k] = pk2(w, w);
    } else if (tid >= 32 && tid < 82) {
        int t2 = tid - 32;
        int ch = t2 / 25, k = t2 % 25;
        float w = w5[(g*2 + ch)*25 + k];
        wp5[ch][k] = pk2(w, w);
    }
    __syncthreads();
    int ty = tid >> 3;             // 0..31
    int tx = (tid & 7) * 4;        // 0,4,...,28
    unsigned long long a3q0 = 0ULL, a3q1 = 0ULL, a5q0 = 0ULL, a5q1 = 0ULL;
    #pragma unroll
    for (int ch = 0; ch < 2; ++ch) {
        const float* t = ch ? t1 : t0;
        #pragma unroll
        for (int ky = 0; ky < 5; ++ky) {
            const float* row = &t[(ty + ky)*40 + tx];
            float4 rA = *(const float4*)row;
            float4 rB = *(const float4*)(row + 4);
            float r0 = rA.x, r1 = rA.y, r2 = rA.z, r3 = rA.w;
            float r4 = rB.x, r5 = rB.y, r6 = rB.z, r7 = rB.w;
            unsigned long long p0 = pk2(r0, r1), p1 = pk2(r1, r2), p2 = pk2(r2, r3);
            unsigned long long p3 = pk2(r3, r4), p4 = pk2(r4, r5), p5 = pk2(r5, r6);
            unsigned long long p6 = pk2(r6, r7);
            unsigned long long pr[7] = { p0, p1, p2, p3, p4, p5, p6 };
            #pragma unroll
            for (int kx = 0; kx < 5; ++kx) {
                unsigned long long w = wp5[ch][ky*5 + kx];
                ffma2(a5q0, w, pr[kx]);
                ffma2(a5q1, w, pr[kx + 2]);
            }
            if (ky >= 1 && ky <= 3) {
                #pragma unroll
                for (int kx = 0; kx < 3; ++kx) {
                    unsigned long long w = wp3[ch][(ky - 1)*3 + kx];
                    ffma2(a3q0, w, pr[1 + kx]);
                    ffma2(a3q1, w, pr[3 + kx]);
                }
            }
        }
    }
    int py = ty0 + ty, px = tx0 + tx;
    float2 a30 = upk2(a3q0), a31 = upk2(a3q1);
    float2 a50 = upk2(a5q0), a51 = upk2(a5q1);
    *(float4*)&out[(size_t)(b*128 + g)      * NHW + py*128 + px] = make_float4(a30.x, a30.y, a31.x, a31.y);
    *(float4*)&out[(size_t)(b*128 + 64 + g) * NHW + py*128 + px] = make_float4(a50.x, a50.y, a51.x, a51.y);
}

// ---------------- gram S partials (float4 loads, pitch 516) ----------------
__global__ void gram_s_part_kernel() {
    extern __shared__ unsigned char s_raw[];
    float* sq = (float*)s_raw;           // [16][516]
    float* sk = sq + 16*516;             // [16][516]
    int bh = blockIdx.x;
    int ns = blockIdx.y;
    int tid = threadIdx.x;
    int c = tid >> 4, d = tid & 15;
    const float* qb = d_q + (size_t)bh * HD * NHW + ns * (NHW / NS);
    const float* kb = d_k + (size_t)bh * HD * NHW + ns * (NHW / NS);
    float acc = 0.f, nq = 0.f, nk = 0.f;
    for (int ch = 0; ch < NHW / NS; ch += 512) {
        for (int i = tid; i < 8192; i += 256) {
            int hh = i >> 9, j = i & 511;
            sq[hh*516 + j] = qb[(size_t)hh*NHW + ch + j];
            sk[hh*516 + j] = kb[(size_t)hh*NHW + ch + j];
        }
        __syncthreads();
        #pragma unroll 4
        for (int j = 0; j < 512; j += 4) {
            float4 A = *(const float4*)&sq[c*516 + j];
            float4 B = *(const float4*)&sk[d*516 + j];
            acc += A.x*B.x + A.y*B.y + A.z*B.z + A.w*B.w;
            if (c == d) {
                nq += A.x*A.x + A.y*A.y + A.z*A.z + A.w*A.w;
                nk += B.x*B.x + B.y*B.y + B.z*B.z + B.w*B.w;
            }
        }
        __syncthreads();
    }
    int part = bh * NS + ns;
    d_gsp[part*256 + tid] = acc;
    if (c == d) { d_gsq[part*16 + c] = nq; d_gsk[part*16 + c] = nk; }
}

// ---------------- gram S finalize ----------------
__global__ void attns_finalize_kernel(const float* __restrict__ temp_s) {
    __shared__ float snq[16], snk[16];
    __shared__ float sA[16][17];
    int bh = blockIdx.x;
    int tid = threadIdx.x;
    int c = tid >> 4, d = tid & 15;
    float acc = 0.f;
    #pragma unroll
    for (int ns = 0; ns < NS; ++ns) acc += d_gsp[(bh*NS + ns)*256 + tid];
    if (tid < 16) {
        float nq = 0.f, nk = 0.f;
        #pragma unroll
        for (int ns = 0; ns < NS; ++ns) {
            nq += d_gsq[(bh*NS + ns)*16 + tid];
            nk += d_gsk[(bh*NS + ns)*16 + tid];
        }
        snq[tid] = fmaxf(sqrtf(nq), 1e-12f);
        snk[tid] = fmaxf(sqrtf(nk), 1e-12f);
    }
    __syncthreads();
    sA[c][d] = acc * temp_s[bh & 7] / (snq[c] * snk[d]);
    __syncthreads();
    if (tid < 16) {
        int row = tid;
        float m = -1e30f;
        #pragma unroll
        for (int dd = 0; dd < 16; ++dd) m = fmaxf(m, sA[row][dd]);
        float e[16], s = 0.f;
        #pragma unroll
        for (int dd = 0; dd < 16; ++dd) { e[dd] = expf(sA[row][dd] - m); s += e[dd]; }
        float is = 1.f / s;
        #pragma unroll
        for (int dd = 0; dd < 16; ++dd) d_attns[bh*256 + row*16 + dd] = e[dd] * is;
    }
}

// ---------------- out_s = attn_s @ v -> d_bufT (FFMA2 over cc pairs) ----------------
__global__ void __launch_bounds__(256, 4) apply_attn_s_kernel() {
    __shared__ ulonglong2 At[64];   // [dd][pq]: pq covers cc pairs (4pq..4pq+3)
    int bh = blockIdx.x, nb = blockIdx.y;
    int tid = threadIdx.x;
    if (tid < 64) {
        int dd = tid >> 2, pq = tid & 3;
        const float* Ab = d_attns + bh*256;
        At[tid] = make_ulonglong2(
            pk2(Ab[(4*pq    )*16 + dd], Ab[(4*pq + 1)*16 + dd]),
            pk2(Ab[(4*pq + 2)*16 + dd], Ab[(4*pq + 3)*16 + dd]));
    }
    __syncthreads();
    int n = nb*256 + tid;
    const float* vb = d_v + (size_t)bh * HD * NHW + n;
    unsigned long long o2[8];
    #pragma unroll
    for (int p = 0; p < 8; ++p) o2[p] = 0ULL;
    #pragma unroll
    for (int dd = 0; dd < 16; ++dd) {
        float vv = vb[(size_t)dd * NHW];
        unsigned long long vd = pk2(vv, vv);
        #pragma unroll
        for (int pq = 0; pq < 4; ++pq) {
            ulonglong2 ap = At[dd*4 + pq];
            ffma2(o2[pq*2    ], ap.x, vd);
            ffma2(o2[pq*2 + 1], ap.y, vd);
        }
    }
    float* dst = d_bufT + (size_t)bh * HD * NHW + n;
    #pragma unroll
    for (int p = 0; p < 8; ++p) {
        float2 o = upk2(o2[p]);
        dst[(size_t)(2*p    ) * NHW] = o.x;
        dst[(size_t)(2*p + 1) * NHW] = o.y;
    }
}

// ---------------- final fused projection (fsa + ssa), FFMA2 ----------------
__global__ void final_conv_kernel(const float* __restrict__ pfw, const float* __restrict__ psw,
                                  float* __restrict__ out) {
    extern __shared__ unsigned char s_raw[];
    float* wt = (float*)s_raw;        // [128 ic][134]
    float* xs = wt + 128*134;         // [128 ic][68]
    int tid = threadIdx.x;
    int pp0 = blockIdx.x * 64;
    int b = pp0 >> 14, p0 = pp0 & (NHW-1);
    int ocg = tid >> 4, pxg = tid & 15;
    int ocb = ocg * 8;
    unsigned long long acc2[4][4];
    #pragma unroll
    for (int p = 0; p < 4; ++p)
        #pragma unroll
        for (int v = 0; v < 4; ++v) acc2[p][v] = 0ULL;
    const float* ins[4] = { d_outf, d_outfl, d_bufT, d_outsl };
    for (int pass = 0; pass < 4; ++pass) {
        const float* wsrc = (pass < 2) ? pfw : psw;
        int off = (pass & 1) * 128;
        for (int i = tid; i < 16384; i += 256) {
            int oc = i >> 7, ic = i & 127;
            wt[ic*134 + oc] = wsrc[oc*256 + off + ic];
        }
        const float* in = ins[pass];
        for (int i = tid; i < 8192; i += 256) {
            int cc = i >> 6, px = i & 63;
            xs[cc*68 + px] = in[(size_t)(b*128 + cc) * NHW + p0 + px];
        }
        __syncthreads();
        #pragma unroll 4
        for (int i = 0; i < 128; ++i) {
            float4 xv = *(const float4*)&xs[i*68 + pxg*4];
            unsigned long long xd0 = pk2(xv.x, xv.x);
            unsigned long long xd1 = pk2(xv.y, xv.y);
            unsigned long long xd2 = pk2(xv.z, xv.z);
            unsigned long long xd3 = pk2(xv.w, xv.w);
            const float* wrow = &wt[i*134 + ocb];
            #pragma unroll
            for (int p = 0; p < 4; ++p) {
                unsigned long long w2 = *(const unsigned long long*)&wrow[2*p];
                ffma2(acc2[p][0], w2, xd0);
                ffma2(acc2[p][1], w2, xd1);
                ffma2(acc2[p][2], w2, xd2);
                ffma2(acc2[p][3], w2, xd3);
            }
        }
        __syncthreads();
    }
    #pragma unroll
    for (int p = 0; p < 4; ++p) {
        float2 a0 = upk2(acc2[p][0]), a1 = upk2(acc2[p][1]);
        float2 a2 = upk2(acc2[p][2]), a3 = upk2(acc2[p][3]);
        int oc = ocb + 2*p;
        *(float4*)&out[(size_t)(b*128 + oc    ) * NHW + p0 + pxg*4] = make_float4(a0.x, a1.x, a2.x, a3.x);
        *(float4*)&out[(size_t)(b*128 + oc + 1) * NHW + p0 + pxg*4] = make_float4(a0.y, a1.y, a2.y, a3.y);
    }
}

// ---------------- host launcher ----------------
#define SM_FFT2  ((128*FPITCH + 64) * (int)sizeof(float2))      // 132,608
#define SM_ROW   ((16896 + 8192) * (int)sizeof(float2))         // 200,704
#define SM_GRAMF (16*514 * (int)sizeof(float2))                 //  65,792
#define SM_GRAMS (2*16*516 * (int)sizeof(float))                //  66,048
#define SM_CONV  ((128*134 + 128*68) * (int)sizeof(float))      // 103,424
#define SM_GATE  ((128*65) * (int)sizeof(float2) + (1024 + 1024 + 8*65) * (int)sizeof(float))

extern "C" void kernel_launch(void* const* d_in, const int* in_sizes, int n_in,
                              void* d_out, int out_size) {
    (void)in_sizes; (void)n_in; (void)out_size;
    const float* x       = (const float*)d_in[0];
    const float* temp_f  = (const float*)d_in[1];
    const float* w1      = (const float*)d_in[2];
    const float* b1      = (const float*)d_in[3];
    const float* bn_g    = (const float*)d_in[4];
    const float* bn_b    = (const float*)d_in[5];
    const float* bn_m    = (const float*)d_in[6];
    const float* bn_v    = (const float*)d_in[7];
    const float* w2      = (const float*)d_in[8];
    const float* b2      = (const float*)d_in[9];
    const float* projf_w = (const float*)d_in[10];
    const float* temp_s  = (const float*)d_in[11];
    const float* q1_w = (const float*)d_in[12];
    const float* q1_b = (const float*)d_in[13];
    const float* k1_w = (const float*)d_in[14];
    const float* k1_b = (const float*)d_in[15];
    const float* v1_w = (const float*)d_in[16];
    const float* v1_b = (const float*)d_in[17];
    const float* q3_w = (const float*)d_in[18];
    const float* q5_w = (const float*)d_in[19];
    const float* k3_w = (const float*)d_in[20];
    const float* k5_w = (const float*)d_in[21];
    const float* v3_w = (const float*)d_in[22];
    const float* v5_w = (const float*)d_in[23];
    const float* c3_w = (const float*)d_in[24];
    const float* c5_w = (const float*)d_in[25];
    const float* projs_w = (const float*)d_in[26];
    float* out = (float*)d_out;

    cudaFuncSetAttribute(fft2_fwd_kernel,    cudaFuncAttributeMaxDynamicSharedMemorySize, SM_FFT2);
    cudaFuncSetAttribute(ifft2_abs_kernel,   cudaFuncAttributeMaxDynamicSharedMemorySize, SM_FFT2);
    cudaFuncSetAttribute(ifft_row_kernel,    cudaFuncAttributeMaxDynamicSharedMemorySize, SM_ROW);
    cudaFuncSetAttribute(gram_f_part_kernel, cudaFuncAttributeMaxDynamicSharedMemorySize, SM_GRAMF);
    cudaFuncSetAttribute(gram_s_part_kernel, cudaFuncAttributeMaxDynamicSharedMemorySize, SM_GRAMS);
    cudaFuncSetAttribute(conv1x1_kernel,     cudaFuncAttributeMaxDynamicSharedMemorySize, SM_CONV);
    cudaFuncSetAttribute(final_conv_kernel,  cudaFuncAttributeMaxDynamicSharedMemorySize, SM_CONV);
    cudaFuncSetAttribute(gate_kernel,        cudaFuncAttributeMaxDynamicSharedMemorySize, SM_GATE);

    float *pT, *pQ, *pK, *pV, *pSL, *ptq, *ptk;
    cudaGetSymbolAddress((void**)&pT,  d_bufT);
    cudaGetSymbolAddress((void**)&pQ,  d_q);
    cudaGetSymbolAddress((void**)&pK,  d_k);
    cudaGetSymbolAddress((void**)&pV,  d_v);
    cudaGetSymbolAddress((void**)&pSL, d_outsl);
    cudaGetSymbolAddress((void**)&ptq, d_tq);
    cudaGetSymbolAddress((void**)&ptk, d_tk);
    float* tq = ptq;
    float* tk = ptk;
    float* tv = pT;      // d_bufT: v-temp then out_s (same stream chain via ev_v)

    // One-time creation of fork streams + events (resource init only).
    static cudaStream_t s_sp = nullptr, s_g = nullptr, s_c = nullptr;
    static cudaEvent_t ev_fork = nullptr, ev_fft = nullptr, ev_g = nullptr,
                       ev_v = nullptr, ev_sp = nullptr;
    if (s_sp == nullptr) {
        cudaStreamCreateWithFlags(&s_sp, cudaStreamNonBlocking);
        cudaStreamCreateWithFlags(&s_g,  cudaStreamNonBlocking);
        cudaStreamCreateWithFlags(&s_c,  cudaStreamNonBlocking);
        cudaEventCreateWithFlags(&ev_fork, cudaEventDisableTiming);
        cudaEventCreateWithFlags(&ev_fft,  cudaEventDisableTiming);
        cudaEventCreateWithFlags(&ev_g,    cudaEventDisableTiming);
        cudaEventCreateWithFlags(&ev_v,    cudaEventDisableTiming);
        cudaEventCreateWithFlags(&ev_sp,   cudaEventDisableTiming);
    }

    // ---- fork: spatial chains start immediately ----
    cudaEventRecord(ev_fork, 0);
    cudaStreamWaitEvent(s_sp, ev_fork, 0);
    cudaStreamWaitEvent(s_c,  ev_fork, 0);

    // ---- s_c: x-gconv + v chain (independent of q/k) ----
    gconv_kernel<<<dim3(16, 64, 8), 256, 0, s_c>>>(x, c3_w, c5_w, pSL);
    conv1x1_kernel<<<2048, 256, SM_CONV, s_c>>>(x, v1_w, v1_b, tv);
    gconv_kernel<<<dim3(16, 64, 8), 256, 0, s_c>>>(tv, v3_w, v5_w, pV);
    cudaEventRecord(ev_v, s_c);

    // ---- s_sp: q/k chain -> gramS; apply_s after v ready ----
    conv1x1_kernel<<<2048, 256, SM_CONV, s_sp>>>(x, q1_w, q1_b, tq);
    gconv_kernel<<<dim3(16, 64, 8), 256, 0, s_sp>>>(tq, q3_w, q5_w, pQ);
    conv1x1_kernel<<<2048, 256, SM_CONV, s_sp>>>(x, k1_w, k1_b, tk);
    gconv_kernel<<<dim3(16, 64, 8), 256, 0, s_sp>>>(tk, k3_w, k5_w, pK);
    gram_s_part_kernel<<<dim3(64, NS), 256, SM_GRAMS, s_sp>>>();
    attns_finalize_kernel<<<64, 256, 0, s_sp>>>(temp_s);
    cudaStreamWaitEvent(s_sp, ev_v, 0);
    apply_attn_s_kernel<<<dim3(64, 64), 256, 0, s_sp>>>();   // overwrites d_bufT (out_s)
    cudaEventRecord(ev_sp, s_sp);

    // ---- s0: freq main chain ----
    fft2_fwd_kernel<<<1024, 512, SM_FFT2>>>(x);
    cudaEventRecord(ev_fft, 0);
    cudaStreamWaitEvent(s_g, ev_fft, 0);
    gram_f_part_kernel<<<dim3(64, NS), 256, SM_GRAMF>>>();
    attnf_finalize_kernel<<<64, 256>>>(temp_f);
    apply_attn_f_kernel<<<dim3(64, 64), 256>>>();   // fused with ifft16, writes d_work
    ifft_row_kernel<<<1024, 1024, SM_ROW>>>();

    // ---- s_g: gate sub-chain (concurrent with gramF/apply/ifft_row) ----
    gate_kernel<<<2048, 256, SM_GATE, s_g>>>(w1, b1, bn_g, bn_b, bn_m, bn_v, w2, b2);  // -> d_work2
    ifft2_abs_kernel<<<1024, 512, SM_FFT2, s_g>>>();                                    // d_work2 -> d_outfl
    cudaEventRecord(ev_g, s_g);

    // ---- join: final projection needs all four buffers ----
    cudaStreamWaitEvent(0, ev_g, 0);
    cudaStreamWaitEvent(0, ev_sp, 0);
    final_conv_kernel<<<2048, 256, SM_CONV>>>(projf_w, projs_w, out);
}